// round 10
// baseline (speedup 1.0000x reference)
#include <cuda_runtime.h>
#include <cuda_bf16.h>
#include <math_constants.h>
#include <cstdint>

#define BB 4
#define NPT 256
#define KNN 27
#define XCAT 8160
#define LATENT 256
#define KPFA 12288
#define NSPLIT 16
#define NSPLIT2 16
#define STAT_FIN 4080
#define STAT_SZ  4336

// ---------------- scratch (device globals; zero-init at load, no allocation) ----------------
__device__ float         d_UV   [BB * NPT * 6144];
__device__ float         d_G2   [NPT * 6144];
__device__ float         d_M    [BB * NPT * 3072];
__device__ float         d_yt   [BB * NPT * LATENT];
__device__ float         d_part [NSPLIT * BB * NPT * LATENT];
__device__ float         d_part2[NSPLIT2 * NPT * LATENT];
__device__ __nv_bfloat16 d_A0   [1024 * 128];
__device__ __nv_bfloat16 d_A1   [1024 * 384];
__device__ __nv_bfloat16 d_A2   [1024 * 1152];
__device__ __nv_bfloat16 d_A3a  [1024 * 2304];
__device__ __nv_bfloat16 d_TP3  [256 * 2304];
__device__ __nv_bfloat16 d_AfinA[1024 * KPFA];
__device__ __nv_bfloat16 d_TPfin[256 * KPFA];
__device__ __nv_bfloat16 d_B0   [128 * 128];
__device__ __nv_bfloat16 d_B1   [384 * 384];
__device__ __nv_bfloat16 d_B2   [1536 * 1152];
__device__ __nv_bfloat16 d_B3a  [6144 * 2304];
__device__ __nv_bfloat16 d_B3tp [6144 * 2304];
__device__ __nv_bfloat16 d_BfA  [256 * KPFA];
__device__ __nv_bfloat16 d_BfTP [256 * KPFA];
__device__ int           d_idx  [BB * NPT * KNN];
__device__ double        d_S1   [STAT_SZ];
__device__ double        d_S2   [STAT_SZ];

__device__ __forceinline__ uint32_t smem_u32(const void* p) {
    return (uint32_t)__cvta_generic_to_shared(p);
}

// ---------------- KNN: warp per point, strict-< argmin ----------------
__global__ void knn_kernel(const float* __restrict__ x) {
    int b     = blockIdx.x >> 5;
    int chunk = blockIdx.x & 31;
    int tid   = threadIdx.x;
    int wid   = tid >> 5;
    int lane  = tid & 31;
    int i     = chunk * 8 + wid;

    __shared__ float px[NPT], py[NPT], pz[NPT];
    const float* xb = x + (size_t)b * NPT * 3;
    px[tid] = xb[tid * 3 + 0];
    py[tid] = xb[tid * 3 + 1];
    pz[tid] = xb[tid * 3 + 2];
    __syncthreads();

    float xi = px[i], yi = py[i], zi = pz[i];
    float dloc[8];
    #pragma unroll
    for (int q = 0; q < 8; q++) {
        int j = lane + q * 32;
        float dx = xi - px[j], dy = yi - py[j], dz = zi - pz[j];
        dloc[q] = dx * dx + dy * dy + dz * dz;
    }
    unsigned chosen = 0;
    for (int s = 0; s < KNN; s++) {
        float bd = CUDART_INF_F;
        int   bj = 0x7fffffff;
        #pragma unroll
        for (int q = 0; q < 8; q++) {
            if (chosen & (1u << q)) continue;
            int j = lane + q * 32;
            float d = dloc[q];
            if (d < bd || (d == bd && j < bj)) { bd = d; bj = j; }
        }
        #pragma unroll
        for (int off = 16; off > 0; off >>= 1) {
            float od = __shfl_xor_sync(0xffffffffu, bd, off);
            int   oj = __shfl_xor_sync(0xffffffffu, bj, off);
            if (od < bd || (od == bd && oj < bj)) { bd = od; bj = oj; }
        }
        if ((bj & 31) == lane) chosen |= (1u << (bj >> 5));
        if (lane == 0) d_idx[((size_t)(b * NPT + i)) * KNN + s] = bj;
    }
}

// ---------------- element helpers for prep ----------------
__device__ __forceinline__ __nv_bfloat16 convB_elem(
    const float* __restrict__ w, int cout, int chFull, int c0, int Csub,
    int Kpad, int i, int mode)
{
    int r = i / Kpad, k = i % Kpad;
    int kk = (k < Csub) ? k : (k < 2 * Csub ? k - Csub : (k < 3 * Csub ? k - 2 * Csub : -1));
    float f = 0.f;
    if (kk >= 0) {
        int c = c0 + kk;
        if (mode) {
            if (r < cout) f = w[(size_t)r * 2 * chFull + c];
            else if (r < 2 * cout)
                f = w[(size_t)(r - cout) * 2 * chFull + chFull + c] - w[(size_t)(r - cout) * 2 * chFull + c];
        } else {
            f = w[(size_t)r * chFull + c];
        }
    }
    if (kk < 0) return __float2bfloat16(0.f);
    if (k < 2 * Csub) return __float2bfloat16(f);
    __nv_bfloat16 h = __float2bfloat16(f);
    return __float2bfloat16(f - __bfloat162float(h));
}

__device__ __forceinline__ __nv_bfloat16 convBfin_elem(
    const float* __restrict__ w4, int isTP, int i)
{
    int r = i / KPFA, k = i % KPFA;
    int kk = (k < 4080) ? k : (k < 8160 ? k - 4080 : (k < 12240 ? k - 8160 : -1));
    float f = 0.f;
    if (kk >= 0) {
        int l = (kk < 48) ? 0 : (kk < 240) ? 1 : (kk < 1008) ? 2 : 3;
        const int aoff[4] = {0, 48, 240, 1008};
        const int xoff[4] = {0, 96, 480, 2016};
        const int co[4]   = {48, 192, 768, 3072};
        int c = xoff[l] + (kk - aoff[l]) + (isTP ? co[l] : 0);
        f = w4[(size_t)r * XCAT + c];
    }
    if (kk < 0) return __float2bfloat16(0.f);
    if (k < 8160) return __float2bfloat16(f);
    __nv_bfloat16 h = __float2bfloat16(f);
    return __float2bfloat16(f - __bfloat162float(h));
}

// ---------------- mega prep: A0 + all B conversions + stat zero, ONE launch ----------------
#define PC0 131072            // A0: 1024*128
#define PC1 (PC0 + 16384)     // B0: 128*128
#define PC2 (PC1 + 147456)    // B1: 384*384
#define PC3 (PC2 + 1769472)   // B2: 1536*1152
#define PC4 (PC3 + 14155776)  // B3a: 6144*2304
#define PC5 (PC4 + 14155776)  // B3tp
#define PC6 (PC5 + 3145728)   // BfA: 256*12288
#define PC7 (PC6 + 3145728)   // BfTP
#define PC8 (PC7 + STAT_SZ)   // stats zero
#define PREP_TOT PC8

__global__ void prep_all(const float* __restrict__ x,
                         const float* __restrict__ w0, const float* __restrict__ w1,
                         const float* __restrict__ w2, const float* __restrict__ w3,
                         const float* __restrict__ w4) {
    int idx = blockIdx.x * 256 + threadIdx.x;
    if (idx >= PREP_TOT) return;
    if (idx < PC0) {
        int r = idx >> 7, k = idx & 127;
        __nv_bfloat16 o;
        if (k < 3) {
            o = __float2bfloat16(x[r * 3 + k]);
        } else if (k < 6) {
            float f = x[r * 3 + (k - 3)];
            __nv_bfloat16 h = __float2bfloat16(f);
            o = __float2bfloat16(f - __bfloat162float(h));
        } else if (k < 9) {
            o = __float2bfloat16(x[r * 3 + (k - 6)]);
        } else {
            o = __float2bfloat16(0.f);
        }
        d_A0[idx] = o;
    } else if (idx < PC1) {
        int i = idx - PC0;
        d_B0[i] = convB_elem(w0, 48, 3, 0, 3, 128, i, 1);
    } else if (idx < PC2) {
        int i = idx - PC1;
        d_B1[i] = convB_elem(w1, 192, 96, 0, 96, 384, i, 1);
    } else if (idx < PC3) {
        int i = idx - PC2;
        d_B2[i] = convB_elem(w2, 768, 384, 0, 384, 1152, i, 1);
    } else if (idx < PC4) {
        int i = idx - PC3;
        d_B3a[i] = convB_elem(w3, 3072, 1536, 0, 768, 2304, i, 1);
    } else if (idx < PC5) {
        int i = idx - PC4;
        d_B3tp[i] = convB_elem(w3, 3072, 1536, 768, 768, 2304, i, 1);
    } else if (idx < PC6) {
        int i = idx - PC5;
        d_BfA[i] = convBfin_elem(w4, 0, i);
    } else if (idx < PC7) {
        int i = idx - PC6;
        d_BfTP[i] = convBfin_elem(w4, 1, i);
    } else {
        int i = idx - PC7;
        d_S1[i] = 0.0; d_S2[i] = 0.0;
    }
}

// ---------------- bf16 HMMA GEMM, 3-stage cp.async pipeline, dual-set capable ----------------
#define SW(off) ((off) ^ (((off) >> 3) & 0x70))
#define NSTAGE 3
#define STG_BYTES 32768

__device__ __forceinline__ void issue_stage(
    const __nv_bfloat16* Ag, int ld, const __nv_bfloat16* Bg,
    uint32_t sA, uint32_t sB, int tid)
{
    #pragma unroll
    for (int q = 0; q < 4; q++) {
        int u = tid + q * 256;
        int r = u >> 3, c16 = u & 7;
        uint32_t off = SW((uint32_t)(r * 128 + c16 * 16));
        asm volatile("cp.async.cg.shared.global [%0], [%1], 16;"
                     :: "r"(sA + off), "l"(Ag + (size_t)r * ld + c16 * 8));
        asm volatile("cp.async.cg.shared.global [%0], [%1], 16;"
                     :: "r"(sB + off), "l"(Bg + (size_t)r * ld + c16 * 8));
    }
}

__global__ __launch_bounds__(256, 1) void gemm_mma(
    const __nv_bfloat16* __restrict__ A,
    const __nv_bfloat16* __restrict__ B,
    float* __restrict__ C,
    const __nv_bfloat16* __restrict__ A2,
    const __nv_bfloat16* __restrict__ B2,
    float* __restrict__ C2,
    int ld, int ldc, int Nc, int yMain,
    int totCh, int chPer, long long ss1, long long ss2,
    const float* __restrict__ addSrc)
{
    extern __shared__ __align__(128) unsigned char dyn[];
    uint32_t sb = smem_u32(dyn);

    int tid  = threadIdx.x;
    int wid  = tid >> 5;
    int lane = tid & 31;

    int yy = blockIdx.y;
    long long ss = ss1;
    if (yy >= yMain) { yy -= yMain; A = A2; B = B2; C = C2; ss = ss2; }
    int m0 = yy * 128, n0 = blockIdx.x * 128;
    int split = blockIdx.z;
    C += (long long)split * ss;
    int ks = split * chPer;
    int ke = min(ks + chPer, totCh);
    int nch = ke - ks;

    int wm0 = (wid >> 1) * 32;
    int wn0 = (wid & 1) * 64;

    float acc[2][8][4];
    #pragma unroll
    for (int i = 0; i < 2; i++)
        #pragma unroll
        for (int j = 0; j < 8; j++)
            #pragma unroll
            for (int c = 0; c < 4; c++) acc[i][j][c] = 0.f;

    const __nv_bfloat16* Abase = A + (size_t)m0 * ld;
    const __nv_bfloat16* Bbase = B + (size_t)n0 * ld;

    #pragma unroll
    for (int s = 0; s < NSTAGE - 1; s++) {
        if (s < nch)
            issue_stage(Abase + (size_t)(ks + s) * 64, ld,
                        Bbase + (size_t)(ks + s) * 64,
                        sb + s * STG_BYTES, sb + s * STG_BYTES + 16384, tid);
        asm volatile("cp.async.commit_group;");
    }

    #pragma unroll 1
    for (int t = 0; t < nch; t++) {
        asm volatile("cp.async.wait_group %0;" :: "n"(NSTAGE - 2));
        __syncthreads();

        {
            int s = t + NSTAGE - 1;
            if (s < nch) {
                uint32_t sbase = sb + (s % NSTAGE) * STG_BYTES;
                issue_stage(Abase + (size_t)(ks + s) * 64, ld,
                            Bbase + (size_t)(ks + s) * 64,
                            sbase, sbase + 16384, tid);
            }
            asm volatile("cp.async.commit_group;");
        }

        uint32_t sbA = sb + (t % NSTAGE) * STG_BYTES;
        uint32_t sbB = sbA + 16384;

        #pragma unroll
        for (int kkstep = 0; kkstep < 4; kkstep++) {
            uint32_t ra0[4], ra1[4], rb[4][4];
            int kb = kkstep * 32;
            {
                int r = lane & 7, sel = lane >> 3;
                int m = wm0 + r + (sel & 1) * 8;
                uint32_t off = SW((uint32_t)(m * 128 + kb + (sel >> 1) * 16));
                asm volatile("ldmatrix.sync.aligned.m8n8.x4.shared.b16 {%0,%1,%2,%3}, [%4];"
                             : "=r"(ra0[0]), "=r"(ra0[1]), "=r"(ra0[2]), "=r"(ra0[3])
                             : "r"(sbA + off));
                uint32_t off2 = SW((uint32_t)((m + 16) * 128 + kb + (sel >> 1) * 16));
                asm volatile("ldmatrix.sync.aligned.m8n8.x4.shared.b16 {%0,%1,%2,%3}, [%4];"
                             : "=r"(ra1[0]), "=r"(ra1[1]), "=r"(ra1[2]), "=r"(ra1[3])
                             : "r"(sbA + off2));
            }
            #pragma unroll
            for (int g = 0; g < 4; g++) {
                int r = lane & 7, sel = lane >> 3;
                int n = wn0 + g * 16 + r + (sel >> 1) * 8;
                uint32_t off = SW((uint32_t)(n * 128 + kb + (sel & 1) * 16));
                asm volatile("ldmatrix.sync.aligned.m8n8.x4.shared.b16 {%0,%1,%2,%3}, [%4];"
                             : "=r"(rb[g][0]), "=r"(rb[g][1]), "=r"(rb[g][2]), "=r"(rb[g][3])
                             : "r"(sbB + off));
            }
            #pragma unroll
            for (int g = 0; g < 4; g++) {
                #pragma unroll
                for (int half = 0; half < 2; half++) {
                    int j = g * 2 + half;
                    uint32_t b0 = rb[g][half * 2], b1 = rb[g][half * 2 + 1];
                    asm volatile(
                        "mma.sync.aligned.m16n8k16.row.col.f32.bf16.bf16.f32 "
                        "{%0,%1,%2,%3}, {%4,%5,%6,%7}, {%8,%9}, {%0,%1,%2,%3};"
                        : "+f"(acc[0][j][0]), "+f"(acc[0][j][1]),
                          "+f"(acc[0][j][2]), "+f"(acc[0][j][3])
                        : "r"(ra0[0]), "r"(ra0[1]), "r"(ra0[2]), "r"(ra0[3]),
                          "r"(b0), "r"(b1));
                    asm volatile(
                        "mma.sync.aligned.m16n8k16.row.col.f32.bf16.bf16.f32 "
                        "{%0,%1,%2,%3}, {%4,%5,%6,%7}, {%8,%9}, {%0,%1,%2,%3};"
                        : "+f"(acc[1][j][0]), "+f"(acc[1][j][1]),
                          "+f"(acc[1][j][2]), "+f"(acc[1][j][3])
                        : "r"(ra1[0]), "r"(ra1[1]), "r"(ra1[2]), "r"(ra1[3]),
                          "r"(b0), "r"(b1));
                }
            }
        }
    }

    #pragma unroll
    for (int mi = 0; mi < 2; mi++) {
        int mlo = m0 + wm0 + mi * 16 + (lane >> 2);
        #pragma unroll
        for (int j = 0; j < 8; j++) {
            int n = n0 + wn0 + j * 8 + (lane & 3) * 2;
            if (n < Nc) {
                float2 v0 = make_float2(acc[mi][j][0], acc[mi][j][1]);
                float2 v1 = make_float2(acc[mi][j][2], acc[mi][j][3]);
                if (addSrc) {
                    float2 a0 = *reinterpret_cast<const float2*>(
                        addSrc + (size_t)(mlo & 255) * ldc + n);
                    float2 a1 = *reinterpret_cast<const float2*>(
                        addSrc + (size_t)((mlo + 8) & 255) * ldc + n);
                    v0.x += a0.x; v0.y += a0.y;
                    v1.x += a1.x; v1.y += a1.y;
                }
                *reinterpret_cast<float2*>(C + (size_t)mlo * ldc + n) = v0;
                *reinterpret_cast<float2*>(C + (size_t)(mlo + 8) * ldc + n) = v1;
            }
        }
    }
}

// ---------------- gather + channel stats + max over k (float2, 2 channels/thread) ----------------
__global__ __launch_bounds__(128) void gather_stats_max(int cout, int bn_per_blk, int statOff) {
    int p = blockIdx.x * 128 + threadIdx.x;     // channel-pair index
    int halfc = cout >> 1;
    bool active = (p < halfc);
    int o = p * 2;
    int twoc = 2 * cout;
    int bnStart = blockIdx.y * bn_per_blk;
    double s1a = 0.0, s1b = 0.0, s2a = 0.0, s2b = 0.0;

    for (int t = 0; t < bn_per_blk; t++) {
        int bn = bnStart + t;
        int b  = bn >> 8;
        const int* ip = d_idx + (size_t)bn * KNN;
        if (!active) continue;
        float2 v = *reinterpret_cast<const float2*>(d_UV + (size_t)bn * twoc + cout + o);
        float mxx = -CUDART_INF_F, mxy = -CUDART_INF_F;
        float sx = 0.f, sy = 0.f, qx = 0.f, qy = 0.f;
        #pragma unroll
        for (int k = 0; k < KNN; k++) {
            int j = ip[k];
            float2 u = *reinterpret_cast<const float2*>(
                d_UV + ((size_t)(b * NPT + j)) * twoc + o);
            mxx = fmaxf(mxx, u.x); mxy = fmaxf(mxy, u.y);
            sx += u.x; sy += u.y;
            qx += u.x * u.x; qy += u.y * u.y;
        }
        *reinterpret_cast<float2*>(d_M + (size_t)bn * cout + o) =
            make_float2(mxx + v.x, mxy + v.y);
        s1a += (double)(sx + (float)KNN * v.x);
        s1b += (double)(sy + (float)KNN * v.y);
        s2a += (double)(qx + 2.f * v.x * sx + (float)KNN * v.x * v.x);
        s2b += (double)(qy + 2.f * v.y * sy + (float)KNN * v.y * v.y);
    }
    if (active) {
        atomicAdd(&d_S1[statOff + o], s1a);
        atomicAdd(&d_S1[statOff + o + 1], s1b);
        atomicAdd(&d_S2[statOff + o], s2a);
        atomicAdd(&d_S2[statOff + o + 1], s2b);
    }
}

// ---------------- activation + temporal pool + bf16 hi/lo operand writes ----------------
__global__ void act_pool(int cout, int aoffG, int KpNext,
                         __nv_bfloat16* __restrict__ nextA,
                         __nv_bfloat16* __restrict__ tpA, int splitMode,
                         int statOff, const float* __restrict__ g,
                         const float* __restrict__ beta, float invcnt) {
    int idx = blockIdx.x * blockDim.x + threadIdx.x;
    if (idx >= NPT * cout) return;
    int o = idx % cout, n = idx / cout;

    float mean = (float)(d_S1[statOff + o] * (double)invcnt);
    float var  = (float)(d_S2[statOff + o] * (double)invcnt) - mean * mean;
    float sc = g[o] * rsqrtf(var + 1e-5f);
    float bi = beta[o] - mean * sc;

    float a[4];
    #pragma unroll
    for (int bb = 0; bb < 4; bb++) {
        float m = d_M[(size_t)(bb * NPT + n) * cout + o];
        float y = m * sc + bi;
        a[bb] = (y >= 0.f) ? y : 0.2f * y;
    }
    float tp = 0.5f * (a[0] + a[1]);
    __nv_bfloat16 tph = __float2bfloat16(tp);
    __nv_bfloat16 tpl = __float2bfloat16(tp - __bfloat162float(tph));
    int C2 = 2 * cout;

    if (splitMode && tpA) {
        __nv_bfloat16* tr = tpA + (size_t)n * KpNext;
        tr[o] = tph; tr[cout + o] = tpl; tr[2 * cout + o] = tph;
    }
    {
        __nv_bfloat16* tf = d_TPfin + (size_t)n * KPFA;
        tf[aoffG + o] = tph; tf[4080 + aoffG + o] = tpl; tf[8160 + aoffG + o] = tph;
    }

    #pragma unroll
    for (int bb = 0; bb < 4; bb++) {
        __nv_bfloat16 vh = __float2bfloat16(a[bb]);
        __nv_bfloat16 vl = __float2bfloat16(a[bb] - __bfloat162float(vh));
        size_t r = (size_t)(bb * NPT + n);
        if (nextA) {
            __nv_bfloat16* row = nextA + r * KpNext;
            if (splitMode) {
                row[o] = vh; row[cout + o] = vl; row[2 * cout + o] = vh;
            } else {
                row[o] = vh;          row[cout + o] = tph;
                row[C2 + o] = vl;     row[C2 + cout + o] = tpl;
                row[2 * C2 + o] = vh; row[2 * C2 + cout + o] = tph;
            }
        }
        __nv_bfloat16* fr = d_AfinA + r * KPFA;
        fr[aoffG + o] = vh; fr[4080 + aoffG + o] = vl; fr[8160 + aoffG + o] = vh;
    }
}

// ---------------- split-K reduce + tp broadcast ----------------
__global__ void reduceK() {
    int idx = blockIdx.x * 256 + threadIdx.x;
    if (idx >= BB * NPT * LATENT) return;
    float s = 0.f;
    #pragma unroll
    for (int p = 0; p < NSPLIT; p++) s += d_part[(size_t)p * BB * NPT * LATENT + idx];
    int n = (idx >> 8) & 255, o = idx & 255;
    float t = 0.f;
    #pragma unroll
    for (int p = 0; p < NSPLIT2; p++) t += d_part2[(size_t)p * NPT * LATENT + n * LATENT + o];
    d_yt[idx] = s + t;
}

// ---------------- final-layer stats ----------------
__global__ __launch_bounds__(256) void final_stats() {
    int o = blockIdx.x;
    int tid = threadIdx.x;
    double s = 0.0, sq = 0.0;
    for (int r = tid; r < BB * NPT; r += 256) {
        float v = d_yt[(size_t)r * LATENT + o];
        s += (double)v;
        sq += (double)v * (double)v;
    }
    __shared__ double sh1[256], sh2[256];
    sh1[tid] = s; sh2[tid] = sq;
    __syncthreads();
    for (int st = 128; st > 0; st >>= 1) {
        if (tid < st) { sh1[tid] += sh1[tid + st]; sh2[tid] += sh2[tid + st]; }
        __syncthreads();
    }
    if (tid == 0) { d_S1[STAT_FIN + o] = sh1[0]; d_S2[STAT_FIN + o] = sh2[0]; }
}

// ---------------- write output: (bb, o, n), BN affine inline ----------------
__global__ void write_out(float* __restrict__ out, const float* __restrict__ g,
                          const float* __restrict__ beta) {
    int idx = blockIdx.x * blockDim.x + threadIdx.x;
    if (idx >= BB * LATENT * NPT) return;
    int n  = idx % NPT;
    int o  = (idx / NPT) % LATENT;
    int bb = idx / (NPT * LATENT);
    float invcnt = 1.f / (float)(BB * NPT);
    float mean = (float)(d_S1[STAT_FIN + o] * (double)invcnt);
    float var  = (float)(d_S2[STAT_FIN + o] * (double)invcnt) - mean * mean;
    float sc = g[o] * rsqrtf(var + 1e-5f);
    float bi = beta[o] - mean * sc;
    float v = d_yt[(size_t)(bb * NPT + n) * LATENT + o];
    float y = v * sc + bi;
    out[idx] = (y >= 0.f) ? y : 0.2f * y;
}

// ---------------- orchestration ----------------
extern "C" void kernel_launch(void* const* d_in, const int* in_sizes, int n_in,
                              void* d_out, int out_size) {
    const float* x = (const float*)d_in[0];
    const float* w[5]; const float* g[5]; const float* bt[5];
    for (int i = 0; i < 5; i++) {
        w[i]  = (const float*)d_in[1 + 3 * i];
        g[i]  = (const float*)d_in[2 + 3 * i];
        bt[i] = (const float*)d_in[3 + 3 * i];
    }
    float* out = (float*)d_out;

    float *UV_p, *G2_p, *part_p, *part2_p;
    __nv_bfloat16 *AfinA_p, *TPfin_p, *A0_p, *A1_p, *A2_p, *A3a_p, *TP3_p;
    __nv_bfloat16 *B0_p, *B1_p, *B2_p, *B3a_p, *B3tp_p, *BfA_p, *BfTP_p;
    cudaGetSymbolAddress((void**)&UV_p,    d_UV);
    cudaGetSymbolAddress((void**)&G2_p,    d_G2);
    cudaGetSymbolAddress((void**)&part_p,  d_part);
    cudaGetSymbolAddress((void**)&part2_p, d_part2);
    cudaGetSymbolAddress((void**)&AfinA_p, d_AfinA);
    cudaGetSymbolAddress((void**)&TPfin_p, d_TPfin);
    cudaGetSymbolAddress((void**)&A0_p,    d_A0);
    cudaGetSymbolAddress((void**)&A1_p,    d_A1);
    cudaGetSymbolAddress((void**)&A2_p,    d_A2);
    cudaGetSymbolAddress((void**)&A3a_p,   d_A3a);
    cudaGetSymbolAddress((void**)&TP3_p,   d_TP3);
    cudaGetSymbolAddress((void**)&B0_p,    d_B0);
    cudaGetSymbolAddress((void**)&B1_p,    d_B1);
    cudaGetSymbolAddress((void**)&B2_p,    d_B2);
    cudaGetSymbolAddress((void**)&B3a_p,   d_B3a);
    cudaGetSymbolAddress((void**)&B3tp_p,  d_B3tp);
    cudaGetSymbolAddress((void**)&BfA_p,   d_BfA);
    cudaGetSymbolAddress((void**)&BfTP_p,  d_BfTP);

    cudaFuncSetAttribute(gemm_mma, cudaFuncAttributeMaxDynamicSharedMemorySize,
                         NSTAGE * STG_BYTES);

    prep_all<<<(PREP_TOT + 255) / 256, 256>>>(x, w[0], w[1], w[2], w[3], w[4]);
    knn_kernel<<<BB * 32, 256>>>(x);

    const int M = BB * NPT;  // 1024
    const long long BIG = 1 << 29;

    // ---- layers 0..2 ----
    const int coL[3]   = {48, 192, 768};
    const int kpadL[3] = {128, 384, 1152};
    const int npadL[3] = {128, 384, 1536};
    const int statL[3] = {0, 48, 240};
    __nv_bfloat16* AbufL[3] = {A0_p, A1_p, A2_p};
    __nv_bfloat16* BbufL[3] = {B0_p, B1_p, B2_p};

    for (int l = 0; l < 3; l++) {
        int twoc = 2 * coL[l];
        int Kp = kpadL[l], Np = npadL[l];
        int totCh = Kp / 64;

        gemm_mma<<<dim3(Np / 128, M / 128, 1), 256, NSTAGE * STG_BYTES>>>(
            AbufL[l], BbufL[l], UV_p, nullptr, nullptr, nullptr,
            Kp, twoc, twoc, 1 << 20, totCh, totCh, 0, 0, nullptr);

        dim3 gg(((coL[l] >> 1) + 127) / 128, M / 8);
        gather_stats_max<<<gg, 128>>>(coL[l], 8, statL[l]);

        if (l < 2) {
            act_pool<<<(NPT * coL[l] + 255) / 256, 256>>>(
                coL[l], statL[l], kpadL[l + 1], AbufL[l + 1], (__nv_bfloat16*)nullptr, 0,
                statL[l], g[l], bt[l], 1.f / (float)(M * KNN));
        } else {
            act_pool<<<(NPT * coL[l] + 255) / 256, 256>>>(
                coL[l], statL[l], 2304, A3a_p, TP3_p, 1,
                statL[l], g[l], bt[l], 1.f / (float)(M * KNN));
        }
    }

    // ---- layer 3: tp GEMM (broadcast source), then main GEMM + broadcast add ----
    {
        int Kp = 2304, Np = 6144, totCh = Kp / 64;  // 36 chunks
        gemm_mma<<<dim3(Np / 128, 2, 1), 256, NSTAGE * STG_BYTES>>>(
            TP3_p, B3tp_p, G2_p, nullptr, nullptr, nullptr,
            Kp, 6144, 6144, 1 << 20, totCh, totCh, 0, 0, nullptr);
        gemm_mma<<<dim3(Np / 128, M / 128, 1), 256, NSTAGE * STG_BYTES>>>(
            A3a_p, B3a_p, UV_p, nullptr, nullptr, nullptr,
            Kp, 6144, 6144, 1 << 20, totCh, totCh, 0, 0, G2_p);

        dim3 gg((1536 + 127) / 128, M / 8);
        gather_stats_max<<<gg, 128>>>(3072, 8, 1008);
        act_pool<<<(NPT * 3072 + 255) / 256, 256>>>(
            3072, 1008, 0, (__nv_bfloat16*)nullptr, (__nv_bfloat16*)nullptr, 0,
            1008, g[3], bt[3], 1.f / (float)(M * KNN));
    }

    // ---- final: dual GEMM in ONE launch (y 0-7 = a-part, y 8-9 = tp-part) ----
    {
        int totCh = KPFA / 64;     // 192 chunks
        int chPer = totCh / NSPLIT; // 12
        gemm_mma<<<dim3(LATENT / 128, M / 128 + NPT / 128, NSPLIT), 256, NSTAGE * STG_BYTES>>>(
            AfinA_p, BfA_p, part_p, TPfin_p, BfTP_p, part2_p,
            KPFA, LATENT, LATENT, M / 128,
            totCh, chPer, (long long)M * LATENT, (long long)NPT * LATENT, nullptr);
        reduceK<<<(M * LATENT + 255) / 256, 256>>>();
    }
    final_stats<<<LATENT, 256>>>();
    write_out<<<(BB * LATENT * NPT + 255) / 256, 256>>>(out, g[4], bt[4]);
}

// round 11
// speedup vs baseline: 1.4046x; 1.4046x over previous
#include <cuda_runtime.h>
#include <cuda_bf16.h>
#include <math_constants.h>
#include <cstdint>

#define BB 4
#define NPT 256
#define KNN 27
#define XCAT 8160
#define LATENT 256
#define KPFA 12288          // final a-part K (3*4080 -> pad 12288)
#define NSPLIT 16
#define NSPLIT2 16
#define STAT_FIN 4080
#define STAT_SZ  4336

// ---------------- scratch (device globals; zero-init at load, no allocation) ----------------
__device__ float         d_UV   [BB * NPT * 6144];
__device__ float         d_G2   [NPT * 6144];
__device__ float         d_M    [BB * NPT * 3072];
__device__ float         d_yt   [BB * NPT * LATENT];
__device__ float         d_part [NSPLIT * BB * NPT * LATENT];
__device__ float         d_part2[NSPLIT2 * NPT * LATENT];
__device__ __nv_bfloat16 d_A0   [1024 * 128];
__device__ __nv_bfloat16 d_A1   [1024 * 384];
__device__ __nv_bfloat16 d_A2   [1024 * 1152];
__device__ __nv_bfloat16 d_A3a  [1024 * 2304];
__device__ __nv_bfloat16 d_TP3  [256 * 2304];
__device__ __nv_bfloat16 d_AfinA[1024 * KPFA];
__device__ __nv_bfloat16 d_TPfin[256 * KPFA];
__device__ __nv_bfloat16 d_Ba   [6144 * 4096];
__device__ __nv_bfloat16 d_Btp  [6144 * 2304];
__device__ int           d_idx  [BB * NPT * KNN];
__device__ double        d_S1   [STAT_SZ];
__device__ double        d_S2   [STAT_SZ];

__device__ __forceinline__ uint32_t smem_u32(const void* p) {
    return (uint32_t)__cvta_generic_to_shared(p);
}

// ---------------- KNN: warp per point, strict-< argmin ----------------
__global__ void knn_kernel(const float* __restrict__ x) {
    int b     = blockIdx.x >> 5;
    int chunk = blockIdx.x & 31;
    int tid   = threadIdx.x;
    int wid   = tid >> 5;
    int lane  = tid & 31;
    int i     = chunk * 8 + wid;

    __shared__ float px[NPT], py[NPT], pz[NPT];
    const float* xb = x + (size_t)b * NPT * 3;
    px[tid] = xb[tid * 3 + 0];
    py[tid] = xb[tid * 3 + 1];
    pz[tid] = xb[tid * 3 + 2];
    __syncthreads();

    float xi = px[i], yi = py[i], zi = pz[i];
    float dloc[8];
    #pragma unroll
    for (int q = 0; q < 8; q++) {
        int j = lane + q * 32;
        float dx = xi - px[j], dy = yi - py[j], dz = zi - pz[j];
        dloc[q] = dx * dx + dy * dy + dz * dz;
    }
    unsigned chosen = 0;
    for (int s = 0; s < KNN; s++) {
        float bd = CUDART_INF_F;
        int   bj = 0x7fffffff;
        #pragma unroll
        for (int q = 0; q < 8; q++) {
            if (chosen & (1u << q)) continue;
            int j = lane + q * 32;
            float d = dloc[q];
            if (d < bd || (d == bd && j < bj)) { bd = d; bj = j; }
        }
        #pragma unroll
        for (int off = 16; off > 0; off >>= 1) {
            float od = __shfl_xor_sync(0xffffffffu, bd, off);
            int   oj = __shfl_xor_sync(0xffffffffu, bj, off);
            if (od < bd || (od == bd && oj < bj)) { bd = od; bj = oj; }
        }
        if ((bj & 31) == lane) chosen |= (1u << (bj >> 5));
        if (lane == 0) d_idx[((size_t)(b * NPT + i)) * KNN + s] = bj;
    }
}

// ---------------- zero stats arena ----------------
__global__ void zero_stats_all() {
    int i = blockIdx.x * 256 + threadIdx.x;
    if (i < STAT_SZ) { d_S1[i] = 0.0; d_S2[i] = 0.0; }
}

// ---------------- layer-0 A conversion ----------------
__global__ void convA0(const float* __restrict__ src) {
    int idx = blockIdx.x * 256 + threadIdx.x;
    if (idx >= 1024 * 128) return;
    int r = idx >> 7, k = idx & 127;
    __nv_bfloat16 o;
    if (k < 3) {
        o = __float2bfloat16(src[r * 3 + k]);
    } else if (k < 6) {
        float f = src[r * 3 + (k - 3)];
        __nv_bfloat16 h = __float2bfloat16(f);
        o = __float2bfloat16(f - __bfloat162float(h));
    } else if (k < 9) {
        o = __float2bfloat16(src[r * 3 + (k - 6)]);
    } else {
        o = __float2bfloat16(0.f);
    }
    d_A0[idx] = o;
}

// ---------------- B conversion: bf16 [hi|hi|lo] of column slice [c0, c0+Csub) ----------------
__global__ void convB(__nv_bfloat16* __restrict__ dst, const float* __restrict__ w,
                      int cout, int chFull, int c0, int Csub,
                      int Kpad, int Np, int mode) {
    int idx = blockIdx.x * 256 + threadIdx.x;
    if (idx >= Np * Kpad) return;
    int r = idx / Kpad, k = idx % Kpad;
    int kk = (k < Csub) ? k : (k < 2 * Csub ? k - Csub : (k < 3 * Csub ? k - 2 * Csub : -1));
    float f = 0.f;
    if (kk >= 0) {
        int c = c0 + kk;
        if (mode) {
            if (r < cout) f = w[(size_t)r * 2 * chFull + c];
            else if (r < 2 * cout)
                f = w[(size_t)(r - cout) * 2 * chFull + chFull + c] - w[(size_t)(r - cout) * 2 * chFull + c];
        } else {
            f = w[(size_t)r * chFull + c];
        }
    }
    __nv_bfloat16 o;
    if (kk < 0) {
        o = __float2bfloat16(0.f);
    } else if (k < 2 * Csub) {
        o = __float2bfloat16(f);
    } else {
        __nv_bfloat16 h = __float2bfloat16(f);
        o = __float2bfloat16(f - __bfloat162float(h));
    }
    dst[(size_t)r * Kpad + k] = o;
}

// ---------------- final B conversion: w4 a-columns or tp-columns -> [hi|hi|lo] ----------------
__global__ void convBfin(__nv_bfloat16* __restrict__ dst, const float* __restrict__ w4, int isTP) {
    int idx = blockIdx.x * 256 + threadIdx.x;
    if (idx >= LATENT * KPFA) return;
    int r = idx / KPFA, k = idx % KPFA;
    int kk = (k < 4080) ? k : (k < 8160 ? k - 4080 : (k < 12240 ? k - 8160 : -1));
    float f = 0.f;
    if (kk >= 0) {
        int l = (kk < 48) ? 0 : (kk < 240) ? 1 : (kk < 1008) ? 2 : 3;
        const int aoff[4] = {0, 48, 240, 1008};
        const int xoff[4] = {0, 96, 480, 2016};
        const int co[4]   = {48, 192, 768, 3072};
        int c = xoff[l] + (kk - aoff[l]) + (isTP ? co[l] : 0);
        f = w4[(size_t)r * XCAT + c];
    }
    __nv_bfloat16 o;
    if (kk < 0) {
        o = __float2bfloat16(0.f);
    } else if (k < 8160) {
        o = __float2bfloat16(f);
    } else {
        __nv_bfloat16 h = __float2bfloat16(f);
        o = __float2bfloat16(f - __bfloat162float(h));
    }
    dst[idx] = o;
}

// ---------------- bf16 HMMA GEMM, 3-stage cp.async pipeline ----------------
#define SW(off) ((off) ^ (((off) >> 3) & 0x70))
#define NSTAGE 3
#define STG_BYTES 32768

__device__ __forceinline__ void issue_stage(
    const __nv_bfloat16* Ag, int ldA, const __nv_bfloat16* Bg, int ldB,
    uint32_t sA, uint32_t sB, int tid)
{
    #pragma unroll
    for (int q = 0; q < 4; q++) {
        int u = tid + q * 256;
        int r = u >> 3, c16 = u & 7;
        uint32_t off = SW((uint32_t)(r * 128 + c16 * 16));
        asm volatile("cp.async.cg.shared.global [%0], [%1], 16;"
                     :: "r"(sA + off), "l"(Ag + (size_t)r * ldA + c16 * 8));
        asm volatile("cp.async.cg.shared.global [%0], [%1], 16;"
                     :: "r"(sB + off), "l"(Bg + (size_t)r * ldB + c16 * 8));
    }
}

__global__ __launch_bounds__(256, 1) void gemm_mma(
    const __nv_bfloat16* __restrict__ A, int ldA,
    const __nv_bfloat16* __restrict__ B, int ldB,
    float* __restrict__ C, int ldc, int Nc,
    int totCh, int chPer, long long splitStride,
    const float* __restrict__ addSrc)
{
    extern __shared__ __align__(128) unsigned char dyn[];
    uint32_t sb = smem_u32(dyn);

    int tid  = threadIdx.x;
    int wid  = tid >> 5;
    int lane = tid & 31;
    int m0 = blockIdx.y * 128, n0 = blockIdx.x * 128;
    int split = blockIdx.z;
    C += (long long)split * splitStride;
    int ks = split * chPer;
    int ke = min(ks + chPer, totCh);
    int nch = ke - ks;

    int wm0 = (wid >> 1) * 32;
    int wn0 = (wid & 1) * 64;

    float acc[2][8][4];
    #pragma unroll
    for (int i = 0; i < 2; i++)
        #pragma unroll
        for (int j = 0; j < 8; j++)
            #pragma unroll
            for (int c = 0; c < 4; c++) acc[i][j][c] = 0.f;

    const __nv_bfloat16* Abase = A + (size_t)m0 * ldA;
    const __nv_bfloat16* Bbase = B + (size_t)n0 * ldB;

    #pragma unroll
    for (int s = 0; s < NSTAGE - 1; s++) {
        if (s < nch)
            issue_stage(Abase + (size_t)(ks + s) * 64, ldA,
                        Bbase + (size_t)(ks + s) * 64, ldB,
                        sb + s * STG_BYTES, sb + s * STG_BYTES + 16384, tid);
        asm volatile("cp.async.commit_group;");
    }

    #pragma unroll 1
    for (int t = 0; t < nch; t++) {
        asm volatile("cp.async.wait_group %0;" :: "n"(NSTAGE - 2));
        __syncthreads();

        {
            int s = t + NSTAGE - 1;
            if (s < nch) {
                uint32_t sbase = sb + (s % NSTAGE) * STG_BYTES;
                issue_stage(Abase + (size_t)(ks + s) * 64, ldA,
                            Bbase + (size_t)(ks + s) * 64, ldB,
                            sbase, sbase + 16384, tid);
            }
            asm volatile("cp.async.commit_group;");
        }

        uint32_t sbA = sb + (t % NSTAGE) * STG_BYTES;
        uint32_t sbB = sbA + 16384;

        #pragma unroll
        for (int kkstep = 0; kkstep < 4; kkstep++) {
            uint32_t ra0[4], ra1[4], rb[4][4];
            int kb = kkstep * 32;
            {
                int r = lane & 7, sel = lane >> 3;
                int m = wm0 + r + (sel & 1) * 8;
                uint32_t off = SW((uint32_t)(m * 128 + kb + (sel >> 1) * 16));
                asm volatile("ldmatrix.sync.aligned.m8n8.x4.shared.b16 {%0,%1,%2,%3}, [%4];"
                             : "=r"(ra0[0]), "=r"(ra0[1]), "=r"(ra0[2]), "=r"(ra0[3])
                             : "r"(sbA + off));
                uint32_t off2 = SW((uint32_t)((m + 16) * 128 + kb + (sel >> 1) * 16));
                asm volatile("ldmatrix.sync.aligned.m8n8.x4.shared.b16 {%0,%1,%2,%3}, [%4];"
                             : "=r"(ra1[0]), "=r"(ra1[1]), "=r"(ra1[2]), "=r"(ra1[3])
                             : "r"(sbA + off2));
            }
            #pragma unroll
            for (int g = 0; g < 4; g++) {
                int r = lane & 7, sel = lane >> 3;
                int n = wn0 + g * 16 + r + (sel >> 1) * 8;
                uint32_t off = SW((uint32_t)(n * 128 + kb + (sel & 1) * 16));
                asm volatile("ldmatrix.sync.aligned.m8n8.x4.shared.b16 {%0,%1,%2,%3}, [%4];"
                             : "=r"(rb[g][0]), "=r"(rb[g][1]), "=r"(rb[g][2]), "=r"(rb[g][3])
                             : "r"(sbB + off));
            }
            #pragma unroll
            for (int g = 0; g < 4; g++) {
                #pragma unroll
                for (int half = 0; half < 2; half++) {
                    int j = g * 2 + half;
                    uint32_t b0 = rb[g][half * 2], b1 = rb[g][half * 2 + 1];
                    asm volatile(
                        "mma.sync.aligned.m16n8k16.row.col.f32.bf16.bf16.f32 "
                        "{%0,%1,%2,%3}, {%4,%5,%6,%7}, {%8,%9}, {%0,%1,%2,%3};"
                        : "+f"(acc[0][j][0]), "+f"(acc[0][j][1]),
                          "+f"(acc[0][j][2]), "+f"(acc[0][j][3])
                        : "r"(ra0[0]), "r"(ra0[1]), "r"(ra0[2]), "r"(ra0[3]),
                          "r"(b0), "r"(b1));
                    asm volatile(
                        "mma.sync.aligned.m16n8k16.row.col.f32.bf16.bf16.f32 "
                        "{%0,%1,%2,%3}, {%4,%5,%6,%7}, {%8,%9}, {%0,%1,%2,%3};"
                        : "+f"(acc[1][j][0]), "+f"(acc[1][j][1]),
                          "+f"(acc[1][j][2]), "+f"(acc[1][j][3])
                        : "r"(ra1[0]), "r"(ra1[1]), "r"(ra1[2]), "r"(ra1[3]),
                          "r"(b0), "r"(b1));
                }
            }
        }
    }

    #pragma unroll
    for (int mi = 0; mi < 2; mi++) {
        int mlo = m0 + wm0 + mi * 16 + (lane >> 2);
        #pragma unroll
        for (int j = 0; j < 8; j++) {
            int n = n0 + wn0 + j * 8 + (lane & 3) * 2;
            if (n < Nc) {
                float2 v0 = make_float2(acc[mi][j][0], acc[mi][j][1]);
                float2 v1 = make_float2(acc[mi][j][2], acc[mi][j][3]);
                if (addSrc) {
                    float2 a0 = *reinterpret_cast<const float2*>(
                        addSrc + (size_t)(mlo & 255) * ldc + n);
                    float2 a1 = *reinterpret_cast<const float2*>(
                        addSrc + (size_t)((mlo + 8) & 255) * ldc + n);
                    v0.x += a0.x; v0.y += a0.y;
                    v1.x += a1.x; v1.y += a1.y;
                }
                *reinterpret_cast<float2*>(C + (size_t)mlo * ldc + n) = v0;
                *reinterpret_cast<float2*>(C + (size_t)(mlo + 8) * ldc + n) = v1;
            }
        }
    }
}

// ---------------- gather + stats + max: float2 inner, HIGH parallelism (bn_per_blk=2) ----------------
__global__ __launch_bounds__(128) void gather_stats_max(int cout, int bn_per_blk, int statOff) {
    int p = blockIdx.x * 128 + threadIdx.x;     // channel-pair index
    int halfc = cout >> 1;
    bool active = (p < halfc);
    int o = p * 2;
    int twoc = 2 * cout;
    int bnStart = blockIdx.y * bn_per_blk;
    double s1a = 0.0, s1b = 0.0, s2a = 0.0, s2b = 0.0;

    for (int t = 0; t < bn_per_blk; t++) {
        int bn = bnStart + t;
        int b  = bn >> 8;
        const int* ip = d_idx + (size_t)bn * KNN;
        if (!active) continue;
        float2 v = *reinterpret_cast<const float2*>(d_UV + (size_t)bn * twoc + cout + o);
        float mxx = -CUDART_INF_F, mxy = -CUDART_INF_F;
        float sx = 0.f, sy = 0.f, qx = 0.f, qy = 0.f;
        #pragma unroll
        for (int k = 0; k < KNN; k++) {
            int j = ip[k];
            float2 u = *reinterpret_cast<const float2*>(
                d_UV + ((size_t)(b * NPT + j)) * twoc + o);
            mxx = fmaxf(mxx, u.x); mxy = fmaxf(mxy, u.y);
            sx += u.x; sy += u.y;
            qx += u.x * u.x; qy += u.y * u.y;
        }
        *reinterpret_cast<float2*>(d_M + (size_t)bn * cout + o) =
            make_float2(mxx + v.x, mxy + v.y);
        s1a += (double)(sx + (float)KNN * v.x);
        s1b += (double)(sy + (float)KNN * v.y);
        s2a += (double)(qx + 2.f * v.x * sx + (float)KNN * v.x * v.x);
        s2b += (double)(qy + 2.f * v.y * sy + (float)KNN * v.y * v.y);
    }
    if (active) {
        atomicAdd(&d_S1[statOff + o], s1a);
        atomicAdd(&d_S1[statOff + o + 1], s1b);
        atomicAdd(&d_S2[statOff + o], s2a);
        atomicAdd(&d_S2[statOff + o + 1], s2b);
    }
}

// ---------------- activation + temporal pool + bf16 hi/lo operand writes ----------------
__global__ void act_pool(int cout, int aoffG, int KpNext,
                         __nv_bfloat16* __restrict__ nextA,
                         __nv_bfloat16* __restrict__ tpA, int splitMode,
                         int statOff, const float* __restrict__ g,
                         const float* __restrict__ beta, float invcnt) {
    int idx = blockIdx.x * blockDim.x + threadIdx.x;
    if (idx >= NPT * cout) return;
    int o = idx % cout, n = idx / cout;

    float mean = (float)(d_S1[statOff + o] * (double)invcnt);
    float var  = (float)(d_S2[statOff + o] * (double)invcnt) - mean * mean;
    float sc = g[o] * rsqrtf(var + 1e-5f);
    float bi = beta[o] - mean * sc;

    float a[4];
    #pragma unroll
    for (int bb = 0; bb < 4; bb++) {
        float m = d_M[(size_t)(bb * NPT + n) * cout + o];
        float y = m * sc + bi;
        a[bb] = (y >= 0.f) ? y : 0.2f * y;
    }
    float tp = 0.5f * (a[0] + a[1]);
    __nv_bfloat16 tph = __float2bfloat16(tp);
    __nv_bfloat16 tpl = __float2bfloat16(tp - __bfloat162float(tph));
    int C2 = 2 * cout;

    if (splitMode && tpA) {
        __nv_bfloat16* tr = tpA + (size_t)n * KpNext;
        tr[o] = tph; tr[cout + o] = tpl; tr[2 * cout + o] = tph;
    }
    {
        __nv_bfloat16* tf = d_TPfin + (size_t)n * KPFA;
        tf[aoffG + o] = tph; tf[4080 + aoffG + o] = tpl; tf[8160 + aoffG + o] = tph;
    }

    #pragma unroll
    for (int bb = 0; bb < 4; bb++) {
        __nv_bfloat16 vh = __float2bfloat16(a[bb]);
        __nv_bfloat16 vl = __float2bfloat16(a[bb] - __bfloat162float(vh));
        size_t r = (size_t)(bb * NPT + n);
        if (nextA) {
            __nv_bfloat16* row = nextA + r * KpNext;
            if (splitMode) {
                row[o] = vh; row[cout + o] = vl; row[2 * cout + o] = vh;
            } else {
                row[o] = vh;          row[cout + o] = tph;
                row[C2 + o] = vl;     row[C2 + cout + o] = tpl;
                row[2 * C2 + o] = vh; row[2 * C2 + cout + o] = tph;
            }
        }
        __nv_bfloat16* fr = d_AfinA + r * KPFA;
        fr[aoffG + o] = vh; fr[4080 + aoffG + o] = vl; fr[8160 + aoffG + o] = vh;
    }
}

// ---------------- split-K reduce + tp broadcast ----------------
__global__ void reduceK() {
    int idx = blockIdx.x * 256 + threadIdx.x;
    if (idx >= BB * NPT * LATENT) return;
    float s = 0.f;
    #pragma unroll
    for (int p = 0; p < NSPLIT; p++) s += d_part[(size_t)p * BB * NPT * LATENT + idx];
    int n = (idx >> 8) & 255, o = idx & 255;
    float t = 0.f;
    #pragma unroll
    for (int p = 0; p < NSPLIT2; p++) t += d_part2[(size_t)p * NPT * LATENT + n * LATENT + o];
    d_yt[idx] = s + t;
}

// ---------------- final-layer stats ----------------
__global__ __launch_bounds__(256) void final_stats() {
    int o = blockIdx.x;
    int tid = threadIdx.x;
    double s = 0.0, sq = 0.0;
    for (int r = tid; r < BB * NPT; r += 256) {
        float v = d_yt[(size_t)r * LATENT + o];
        s += (double)v;
        sq += (double)v * (double)v;
    }
    __shared__ double sh1[256], sh2[256];
    sh1[tid] = s; sh2[tid] = sq;
    __syncthreads();
    for (int st = 128; st > 0; st >>= 1) {
        if (tid < st) { sh1[tid] += sh1[tid + st]; sh2[tid] += sh2[tid + st]; }
        __syncthreads();
    }
    if (tid == 0) { d_S1[STAT_FIN + o] = sh1[0]; d_S2[STAT_FIN + o] = sh2[0]; }
}

// ---------------- write output: (bb, o, n), BN affine inline ----------------
__global__ void write_out(float* __restrict__ out, const float* __restrict__ g,
                          const float* __restrict__ beta) {
    int idx = blockIdx.x * blockDim.x + threadIdx.x;
    if (idx >= BB * LATENT * NPT) return;
    int n  = idx % NPT;
    int o  = (idx / NPT) % LATENT;
    int bb = idx / (NPT * LATENT);
    float invcnt = 1.f / (float)(BB * NPT);
    float mean = (float)(d_S1[STAT_FIN + o] * (double)invcnt);
    float var  = (float)(d_S2[STAT_FIN + o] * (double)invcnt) - mean * mean;
    float sc = g[o] * rsqrtf(var + 1e-5f);
    float bi = beta[o] - mean * sc;
    float v = d_yt[(size_t)(bb * NPT + n) * LATENT + o];
    float y = v * sc + bi;
    out[idx] = (y >= 0.f) ? y : 0.2f * y;
}

// ---------------- orchestration ----------------
extern "C" void kernel_launch(void* const* d_in, const int* in_sizes, int n_in,
                              void* d_out, int out_size) {
    const float* x = (const float*)d_in[0];
    const float* w[5]; const float* g[5]; const float* bt[5];
    for (int i = 0; i < 5; i++) {
        w[i]  = (const float*)d_in[1 + 3 * i];
        g[i]  = (const float*)d_in[2 + 3 * i];
        bt[i] = (const float*)d_in[3 + 3 * i];
    }
    float* out = (float*)d_out;

    float *UV_p, *G2_p, *part_p, *part2_p;
    __nv_bfloat16 *Ba_p, *Btp_p, *AfinA_p, *TPfin_p, *A0_p, *A1_p, *A2_p, *A3a_p, *TP3_p;
    cudaGetSymbolAddress((void**)&UV_p,    d_UV);
    cudaGetSymbolAddress((void**)&G2_p,    d_G2);
    cudaGetSymbolAddress((void**)&part_p,  d_part);
    cudaGetSymbolAddress((void**)&part2_p, d_part2);
    cudaGetSymbolAddress((void**)&Ba_p,    d_Ba);
    cudaGetSymbolAddress((void**)&Btp_p,   d_Btp);
    cudaGetSymbolAddress((void**)&AfinA_p, d_AfinA);
    cudaGetSymbolAddress((void**)&TPfin_p, d_TPfin);
    cudaGetSymbolAddress((void**)&A0_p,    d_A0);
    cudaGetSymbolAddress((void**)&A1_p,    d_A1);
    cudaGetSymbolAddress((void**)&A2_p,    d_A2);
    cudaGetSymbolAddress((void**)&A3a_p,   d_A3a);
    cudaGetSymbolAddress((void**)&TP3_p,   d_TP3);

    cudaFuncSetAttribute(gemm_mma, cudaFuncAttributeMaxDynamicSharedMemorySize,
                         NSTAGE * STG_BYTES);

    zero_stats_all<<<(STAT_SZ + 255) / 256, 256>>>();
    knn_kernel<<<BB * 32, 256>>>(x);
    convA0<<<(1024 * 128 + 255) / 256, 256>>>(x);

    const int M = BB * NPT;  // 1024
    const int BNB = 2;       // bn per gather block (high parallelism)

    // ---- layers 0..2 ----
    const int chL[3]   = {3, 96, 384};
    const int coL[3]   = {48, 192, 768};
    const int kpadL[3] = {128, 384, 1152};
    const int npadL[3] = {128, 384, 1536};
    const int statL[3] = {0, 48, 240};
    __nv_bfloat16* AbufL[3] = {A0_p, A1_p, A2_p};

    for (int l = 0; l < 3; l++) {
        int twoc = 2 * coL[l];
        int Kp = kpadL[l], Np = npadL[l];
        int totCh = Kp / 64;

        convB<<<((size_t)Np * Kp + 255) / 256, 256>>>(Ba_p, w[l], coL[l], chL[l],
                                                      0, chL[l], Kp, Np, 1);
        dim3 grid(Np / 128, M / 128, 1);
        gemm_mma<<<grid, 256, NSTAGE * STG_BYTES>>>(
            AbufL[l], Kp, Ba_p, Kp, UV_p, twoc, twoc, totCh, totCh, 0, nullptr);

        dim3 gg(((coL[l] >> 1) + 127) / 128, M / BNB);
        gather_stats_max<<<gg, 128>>>(coL[l], BNB, statL[l]);

        if (l < 2) {
            act_pool<<<(NPT * coL[l] + 255) / 256, 256>>>(
                coL[l], statL[l], kpadL[l + 1], AbufL[l + 1], (__nv_bfloat16*)nullptr, 0,
                statL[l], g[l], bt[l], 1.f / (float)(M * KNN));
        } else {
            act_pool<<<(NPT * coL[l] + 255) / 256, 256>>>(
                coL[l], statL[l], 2304, A3a_p, TP3_p, 1,
                statL[l], g[l], bt[l], 1.f / (float)(M * KNN));
        }
    }

    // ---- layer 3: split GEMM (a-part M=1024, tp-part M=256 broadcast) ----
    {
        int Kp = 2304, Np = 6144, totCh = Kp / 64;  // 36 chunks
        convB<<<((size_t)Np * Kp + 255) / 256, 256>>>(Ba_p,  w[3], 3072, 1536, 0,   768, Kp, Np, 1);
        convB<<<((size_t)Np * Kp + 255) / 256, 256>>>(Btp_p, w[3], 3072, 1536, 768, 768, Kp, Np, 1);

        gemm_mma<<<dim3(Np / 128, 2, 1), 256, NSTAGE * STG_BYTES>>>(
            TP3_p, Kp, Btp_p, Kp, G2_p, 6144, 6144, totCh, totCh, 0, nullptr);
        gemm_mma<<<dim3(Np / 128, M / 128, 1), 256, NSTAGE * STG_BYTES>>>(
            A3a_p, Kp, Ba_p, Kp, UV_p, 6144, 6144, totCh, totCh, 0, G2_p);

        dim3 gg((1536 + 127) / 128, M / BNB);
        gather_stats_max<<<gg, 128>>>(3072, BNB, 1008);
        act_pool<<<(NPT * 3072 + 255) / 256, 256>>>(
            3072, 1008, 0, (__nv_bfloat16*)nullptr, (__nv_bfloat16*)nullptr, 0,
            1008, g[3], bt[3], 1.f / (float)(M * KNN));
    }

    // ---- final: Ya = AfinA . BfA^T (split-K 16) + TP broadcast (split-K 16) ----
    {
        int totCh = KPFA / 64;   // 192 chunks
        convBfin<<<((size_t)LATENT * KPFA + 255) / 256, 256>>>(Ba_p,  w[4], 0);
        convBfin<<<((size_t)LATENT * KPFA + 255) / 256, 256>>>(Btp_p, w[4], 1);

        gemm_mma<<<dim3(LATENT / 128, M / 128, NSPLIT), 256, NSTAGE * STG_BYTES>>>(
            AfinA_p, KPFA, Ba_p, KPFA, part_p, LATENT, LATENT,
            totCh, totCh / NSPLIT, (long long)M * LATENT, nullptr);
        gemm_mma<<<dim3(LATENT / 128, NPT / 128, NSPLIT2), 256, NSTAGE * STG_BYTES>>>(
            TPfin_p, KPFA, Btp_p, KPFA, part2_p, LATENT, LATENT,
            totCh, totCh / NSPLIT2, (long long)NPT * LATENT, nullptr);

        reduceK<<<(M * LATENT + 255) / 256, 256>>>();
    }
    final_stats<<<LATENT, 256>>>();
    write_out<<<(BB * LATENT * NPT + 255) / 256, 256>>>(out, g[4], bt[4]);
}

// round 12
// speedup vs baseline: 1.5927x; 1.1339x over previous
#include <cuda_runtime.h>
#include <cuda_bf16.h>
#include <math_constants.h>
#include <cstdint>

#define BB 4
#define NPT 256
#define KNN 27
#define XCAT 8160
#define LATENT 256
#define KPFA 12288
#define NSPLIT 16
#define NSPLIT2 16
#define STAT_FIN 4080
#define STAT_SZ  4336

// ---------------- scratch (device globals; zero-init at load, no allocation) ----------------
__device__ float         d_UV   [BB * NPT * 6144];
__device__ float         d_G2   [NPT * 6144];
__device__ float         d_M    [BB * NPT * 3072];
__device__ float         d_yt   [BB * NPT * LATENT];
__device__ float         d_part [NSPLIT * BB * NPT * LATENT];
__device__ float         d_part2[NSPLIT2 * NPT * LATENT];
__device__ __nv_bfloat16 d_A0   [1024 * 128];
__device__ __nv_bfloat16 d_A1   [1024 * 384];
__device__ __nv_bfloat16 d_A2   [1024 * 1152];
__device__ __nv_bfloat16 d_A3a  [1024 * 2304];
__device__ __nv_bfloat16 d_TP3  [256 * 2304];
__device__ __nv_bfloat16 d_AfinA[1024 * KPFA];
__device__ __nv_bfloat16 d_TPfin[256 * KPFA];
__device__ __nv_bfloat16 d_B0   [128 * 128];
__device__ __nv_bfloat16 d_B1   [384 * 384];
__device__ __nv_bfloat16 d_B2   [1536 * 1152];
__device__ __nv_bfloat16 d_B3a  [6144 * 2304];
__device__ __nv_bfloat16 d_B3tp [6144 * 2304];
__device__ __nv_bfloat16 d_BfA  [256 * KPFA];
__device__ __nv_bfloat16 d_BfTP [256 * KPFA];
__device__ int           d_idx  [BB * NPT * KNN];
__device__ double        d_S1   [STAT_SZ];
__device__ double        d_S2   [STAT_SZ];

__device__ __forceinline__ uint32_t smem_u32(const void* p) {
    return (uint32_t)__cvta_generic_to_shared(p);
}

// ---------------- KNN: warp per point, strict-< argmin ----------------
__global__ void knn_kernel(const float* __restrict__ x) {
    int b     = blockIdx.x >> 5;
    int chunk = blockIdx.x & 31;
    int tid   = threadIdx.x;
    int wid   = tid >> 5;
    int lane  = tid & 31;
    int i     = chunk * 8 + wid;

    __shared__ float px[NPT], py[NPT], pz[NPT];
    const float* xb = x + (size_t)b * NPT * 3;
    px[tid] = xb[tid * 3 + 0];
    py[tid] = xb[tid * 3 + 1];
    pz[tid] = xb[tid * 3 + 2];
    __syncthreads();

    float xi = px[i], yi = py[i], zi = pz[i];
    float dloc[8];
    #pragma unroll
    for (int q = 0; q < 8; q++) {
        int j = lane + q * 32;
        float dx = xi - px[j], dy = yi - py[j], dz = zi - pz[j];
        dloc[q] = dx * dx + dy * dy + dz * dz;
    }
    unsigned chosen = 0;
    for (int s = 0; s < KNN; s++) {
        float bd = CUDART_INF_F;
        int   bj = 0x7fffffff;
        #pragma unroll
        for (int q = 0; q < 8; q++) {
            if (chosen & (1u << q)) continue;
            int j = lane + q * 32;
            float d = dloc[q];
            if (d < bd || (d == bd && j < bj)) { bd = d; bj = j; }
        }
        #pragma unroll
        for (int off = 16; off > 0; off >>= 1) {
            float od = __shfl_xor_sync(0xffffffffu, bd, off);
            int   oj = __shfl_xor_sync(0xffffffffu, bj, off);
            if (od < bd || (od == bd && oj < bj)) { bd = od; bj = oj; }
        }
        if ((bj & 31) == lane) chosen |= (1u << (bj >> 5));
        if (lane == 0) d_idx[((size_t)(b * NPT + i)) * KNN + s] = bj;
    }
}

// ---------------- element helpers for prep ----------------
__device__ __forceinline__ __nv_bfloat16 convB_elem(
    const float* __restrict__ w, int cout, int chFull, int c0, int Csub,
    int Kpad, int i, int mode)
{
    int r = i / Kpad, k = i % Kpad;
    int kk = (k < Csub) ? k : (k < 2 * Csub ? k - Csub : (k < 3 * Csub ? k - 2 * Csub : -1));
    float f = 0.f;
    if (kk >= 0) {
        int c = c0 + kk;
        if (mode) {
            if (r < cout) f = w[(size_t)r * 2 * chFull + c];
            else if (r < 2 * cout)
                f = w[(size_t)(r - cout) * 2 * chFull + chFull + c] - w[(size_t)(r - cout) * 2 * chFull + c];
        } else {
            f = w[(size_t)r * chFull + c];
        }
    }
    if (kk < 0) return __float2bfloat16(0.f);
    if (k < 2 * Csub) return __float2bfloat16(f);
    __nv_bfloat16 h = __float2bfloat16(f);
    return __float2bfloat16(f - __bfloat162float(h));
}

__device__ __forceinline__ __nv_bfloat16 convBfin_elem(
    const float* __restrict__ w4, int isTP, int i)
{
    int r = i / KPFA, k = i % KPFA;
    int kk = (k < 4080) ? k : (k < 8160 ? k - 4080 : (k < 12240 ? k - 8160 : -1));
    float f = 0.f;
    if (kk >= 0) {
        int l = (kk < 48) ? 0 : (kk < 240) ? 1 : (kk < 1008) ? 2 : 3;
        const int aoff[4] = {0, 48, 240, 1008};
        const int xoff[4] = {0, 96, 480, 2016};
        const int co[4]   = {48, 192, 768, 3072};
        int c = xoff[l] + (kk - aoff[l]) + (isTP ? co[l] : 0);
        f = w4[(size_t)r * XCAT + c];
    }
    if (kk < 0) return __float2bfloat16(0.f);
    if (k < 8160) return __float2bfloat16(f);
    __nv_bfloat16 h = __float2bfloat16(f);
    return __float2bfloat16(f - __bfloat162float(h));
}

// ---------------- mega prep: A0 + all B conversions + stat zero, ONE launch ----------------
#define PC0 131072            // A0: 1024*128
#define PC1 (PC0 + 16384)     // B0: 128*128
#define PC2 (PC1 + 147456)    // B1: 384*384
#define PC3 (PC2 + 1769472)   // B2: 1536*1152
#define PC4 (PC3 + 14155776)  // B3a: 6144*2304
#define PC5 (PC4 + 14155776)  // B3tp
#define PC6 (PC5 + 3145728)   // BfA: 256*12288
#define PC7 (PC6 + 3145728)   // BfTP
#define PC8 (PC7 + STAT_SZ)   // stats zero
#define PREP_TOT PC8

__global__ void prep_all(const float* __restrict__ x,
                         const float* __restrict__ w0, const float* __restrict__ w1,
                         const float* __restrict__ w2, const float* __restrict__ w3,
                         const float* __restrict__ w4) {
    int idx = blockIdx.x * 256 + threadIdx.x;
    if (idx >= PREP_TOT) return;
    if (idx < PC0) {
        int r = idx >> 7, k = idx & 127;
        __nv_bfloat16 o;
        if (k < 3) {
            o = __float2bfloat16(x[r * 3 + k]);
        } else if (k < 6) {
            float f = x[r * 3 + (k - 3)];
            __nv_bfloat16 h = __float2bfloat16(f);
            o = __float2bfloat16(f - __bfloat162float(h));
        } else if (k < 9) {
            o = __float2bfloat16(x[r * 3 + (k - 6)]);
        } else {
            o = __float2bfloat16(0.f);
        }
        d_A0[idx] = o;
    } else if (idx < PC1) {
        int i = idx - PC0;
        d_B0[i] = convB_elem(w0, 48, 3, 0, 3, 128, i, 1);
    } else if (idx < PC2) {
        int i = idx - PC1;
        d_B1[i] = convB_elem(w1, 192, 96, 0, 96, 384, i, 1);
    } else if (idx < PC3) {
        int i = idx - PC2;
        d_B2[i] = convB_elem(w2, 768, 384, 0, 384, 1152, i, 1);
    } else if (idx < PC4) {
        int i = idx - PC3;
        d_B3a[i] = convB_elem(w3, 3072, 1536, 0, 768, 2304, i, 1);
    } else if (idx < PC5) {
        int i = idx - PC4;
        d_B3tp[i] = convB_elem(w3, 3072, 1536, 768, 768, 2304, i, 1);
    } else if (idx < PC6) {
        int i = idx - PC5;
        d_BfA[i] = convBfin_elem(w4, 0, i);
    } else if (idx < PC7) {
        int i = idx - PC6;
        d_BfTP[i] = convBfin_elem(w4, 1, i);
    } else {
        int i = idx - PC7;
        d_S1[i] = 0.0; d_S2[i] = 0.0;
    }
}

// ---------------- bf16 HMMA GEMM, 3-stage cp.async pipeline (R9 config) ----------------
#define SW(off) ((off) ^ (((off) >> 3) & 0x70))
#define NSTAGE 3
#define STG_BYTES 32768

__device__ __forceinline__ void issue_stage(
    const __nv_bfloat16* Ag, int ldA, const __nv_bfloat16* Bg, int ldB,
    uint32_t sA, uint32_t sB, int tid)
{
    #pragma unroll
    for (int q = 0; q < 4; q++) {
        int u = tid + q * 256;
        int r = u >> 3, c16 = u & 7;
        uint32_t off = SW((uint32_t)(r * 128 + c16 * 16));
        asm volatile("cp.async.cg.shared.global [%0], [%1], 16;"
                     :: "r"(sA + off), "l"(Ag + (size_t)r * ldA + c16 * 8));
        asm volatile("cp.async.cg.shared.global [%0], [%1], 16;"
                     :: "r"(sB + off), "l"(Bg + (size_t)r * ldB + c16 * 8));
    }
}

__global__ __launch_bounds__(256, 1) void gemm_mma(
    const __nv_bfloat16* __restrict__ A, int ldA,
    const __nv_bfloat16* __restrict__ B, int ldB,
    float* __restrict__ C, int ldc, int Nc,
    int totCh, int chPer, long long splitStride,
    const float* __restrict__ addSrc)
{
    extern __shared__ __align__(128) unsigned char dyn[];
    uint32_t sb = smem_u32(dyn);

    int tid  = threadIdx.x;
    int wid  = tid >> 5;
    int lane = tid & 31;
    int m0 = blockIdx.y * 128, n0 = blockIdx.x * 128;
    int split = blockIdx.z;
    C += (long long)split * splitStride;
    int ks = split * chPer;
    int ke = min(ks + chPer, totCh);
    int nch = ke - ks;

    int wm0 = (wid >> 1) * 32;
    int wn0 = (wid & 1) * 64;

    float acc[2][8][4];
    #pragma unroll
    for (int i = 0; i < 2; i++)
        #pragma unroll
        for (int j = 0; j < 8; j++)
            #pragma unroll
            for (int c = 0; c < 4; c++) acc[i][j][c] = 0.f;

    const __nv_bfloat16* Abase = A + (size_t)m0 * ldA;
    const __nv_bfloat16* Bbase = B + (size_t)n0 * ldB;

    #pragma unroll
    for (int s = 0; s < NSTAGE - 1; s++) {
        if (s < nch)
            issue_stage(Abase + (size_t)(ks + s) * 64, ldA,
                        Bbase + (size_t)(ks + s) * 64, ldB,
                        sb + s * STG_BYTES, sb + s * STG_BYTES + 16384, tid);
        asm volatile("cp.async.commit_group;");
    }

    #pragma unroll 1
    for (int t = 0; t < nch; t++) {
        asm volatile("cp.async.wait_group %0;" :: "n"(NSTAGE - 2));
        __syncthreads();

        {
            int s = t + NSTAGE - 1;
            if (s < nch) {
                uint32_t sbase = sb + (s % NSTAGE) * STG_BYTES;
                issue_stage(Abase + (size_t)(ks + s) * 64, ldA,
                            Bbase + (size_t)(ks + s) * 64, ldB,
                            sbase, sbase + 16384, tid);
            }
            asm volatile("cp.async.commit_group;");
        }

        uint32_t sbA = sb + (t % NSTAGE) * STG_BYTES;
        uint32_t sbB = sbA + 16384;

        #pragma unroll
        for (int kkstep = 0; kkstep < 4; kkstep++) {
            uint32_t ra0[4], ra1[4], rb[4][4];
            int kb = kkstep * 32;
            {
                int r = lane & 7, sel = lane >> 3;
                int m = wm0 + r + (sel & 1) * 8;
                uint32_t off = SW((uint32_t)(m * 128 + kb + (sel >> 1) * 16));
                asm volatile("ldmatrix.sync.aligned.m8n8.x4.shared.b16 {%0,%1,%2,%3}, [%4];"
                             : "=r"(ra0[0]), "=r"(ra0[1]), "=r"(ra0[2]), "=r"(ra0[3])
                             : "r"(sbA + off));
                uint32_t off2 = SW((uint32_t)((m + 16) * 128 + kb + (sel >> 1) * 16));
                asm volatile("ldmatrix.sync.aligned.m8n8.x4.shared.b16 {%0,%1,%2,%3}, [%4];"
                             : "=r"(ra1[0]), "=r"(ra1[1]), "=r"(ra1[2]), "=r"(ra1[3])
                             : "r"(sbA + off2));
            }
            #pragma unroll
            for (int g = 0; g < 4; g++) {
                int r = lane & 7, sel = lane >> 3;
                int n = wn0 + g * 16 + r + (sel >> 1) * 8;
                uint32_t off = SW((uint32_t)(n * 128 + kb + (sel & 1) * 16));
                asm volatile("ldmatrix.sync.aligned.m8n8.x4.shared.b16 {%0,%1,%2,%3}, [%4];"
                             : "=r"(rb[g][0]), "=r"(rb[g][1]), "=r"(rb[g][2]), "=r"(rb[g][3])
                             : "r"(sbB + off));
            }
            #pragma unroll
            for (int g = 0; g < 4; g++) {
                #pragma unroll
                for (int half = 0; half < 2; half++) {
                    int j = g * 2 + half;
                    uint32_t b0 = rb[g][half * 2], b1 = rb[g][half * 2 + 1];
                    asm volatile(
                        "mma.sync.aligned.m16n8k16.row.col.f32.bf16.bf16.f32 "
                        "{%0,%1,%2,%3}, {%4,%5,%6,%7}, {%8,%9}, {%0,%1,%2,%3};"
                        : "+f"(acc[0][j][0]), "+f"(acc[0][j][1]),
                          "+f"(acc[0][j][2]), "+f"(acc[0][j][3])
                        : "r"(ra0[0]), "r"(ra0[1]), "r"(ra0[2]), "r"(ra0[3]),
                          "r"(b0), "r"(b1));
                    asm volatile(
                        "mma.sync.aligned.m16n8k16.row.col.f32.bf16.bf16.f32 "
                        "{%0,%1,%2,%3}, {%4,%5,%6,%7}, {%8,%9}, {%0,%1,%2,%3};"
                        : "+f"(acc[1][j][0]), "+f"(acc[1][j][1]),
                          "+f"(acc[1][j][2]), "+f"(acc[1][j][3])
                        : "r"(ra1[0]), "r"(ra1[1]), "r"(ra1[2]), "r"(ra1[3]),
                          "r"(b0), "r"(b1));
                }
            }
        }
    }

    #pragma unroll
    for (int mi = 0; mi < 2; mi++) {
        int mlo = m0 + wm0 + mi * 16 + (lane >> 2);
        #pragma unroll
        for (int j = 0; j < 8; j++) {
            int n = n0 + wn0 + j * 8 + (lane & 3) * 2;
            if (n < Nc) {
                float2 v0 = make_float2(acc[mi][j][0], acc[mi][j][1]);
                float2 v1 = make_float2(acc[mi][j][2], acc[mi][j][3]);
                if (addSrc) {
                    float2 a0 = *reinterpret_cast<const float2*>(
                        addSrc + (size_t)(mlo & 255) * ldc + n);
                    float2 a1 = *reinterpret_cast<const float2*>(
                        addSrc + (size_t)((mlo + 8) & 255) * ldc + n);
                    v0.x += a0.x; v0.y += a0.y;
                    v1.x += a1.x; v1.y += a1.y;
                }
                *reinterpret_cast<float2*>(C + (size_t)mlo * ldc + n) = v0;
                *reinterpret_cast<float2*>(C + (size_t)(mlo + 8) * ldc + n) = v1;
            }
        }
    }
}

// ---------------- gather + channel stats + max over k (R9 scalar form) ----------------
__global__ __launch_bounds__(128) void gather_stats_max(int cout, int bn_per_blk, int statOff) {
    int o = blockIdx.x * 128 + threadIdx.x;
    int bnStart = blockIdx.y * bn_per_blk;
    bool active = (o < cout);
    int twoc = 2 * cout;
    double s1 = 0.0, s2 = 0.0;

    for (int t = 0; t < bn_per_blk; t++) {
        int bn = bnStart + t;
        int b  = bn >> 8;
        const int* ip = d_idx + (size_t)bn * KNN;
        if (!active) continue;
        float v = d_UV[(size_t)bn * twoc + cout + o];
        float mx = -CUDART_INF_F, s = 0.f, ssq = 0.f;
        #pragma unroll
        for (int k = 0; k < KNN; k++) {
            int j = ip[k];
            float u = d_UV[((size_t)(b * NPT + j)) * twoc + o];
            mx = fmaxf(mx, u);
            s += u;
            ssq += u * u;
        }
        d_M[(size_t)bn * cout + o] = mx + v;
        s1 += (double)(s + (float)KNN * v);
        s2 += (double)(ssq + 2.f * v * s + (float)KNN * v * v);
    }
    if (active) {
        atomicAdd(&d_S1[statOff + o], s1);
        atomicAdd(&d_S2[statOff + o], s2);
    }
}

// ---------------- activation + temporal pool + bf16 hi/lo operand writes ----------------
__global__ void act_pool(int cout, int aoffG, int KpNext,
                         __nv_bfloat16* __restrict__ nextA,
                         __nv_bfloat16* __restrict__ tpA, int splitMode,
                         int statOff, const float* __restrict__ g,
                         const float* __restrict__ beta, float invcnt) {
    int idx = blockIdx.x * blockDim.x + threadIdx.x;
    if (idx >= NPT * cout) return;
    int o = idx % cout, n = idx / cout;

    float mean = (float)(d_S1[statOff + o] * (double)invcnt);
    float var  = (float)(d_S2[statOff + o] * (double)invcnt) - mean * mean;
    float sc = g[o] * rsqrtf(var + 1e-5f);
    float bi = beta[o] - mean * sc;

    float a[4];
    #pragma unroll
    for (int bb = 0; bb < 4; bb++) {
        float m = d_M[(size_t)(bb * NPT + n) * cout + o];
        float y = m * sc + bi;
        a[bb] = (y >= 0.f) ? y : 0.2f * y;
    }
    float tp = 0.5f * (a[0] + a[1]);
    __nv_bfloat16 tph = __float2bfloat16(tp);
    __nv_bfloat16 tpl = __float2bfloat16(tp - __bfloat162float(tph));
    int C2 = 2 * cout;

    if (splitMode && tpA) {
        __nv_bfloat16* tr = tpA + (size_t)n * KpNext;
        tr[o] = tph; tr[cout + o] = tpl; tr[2 * cout + o] = tph;
    }
    {
        __nv_bfloat16* tf = d_TPfin + (size_t)n * KPFA;
        tf[aoffG + o] = tph; tf[4080 + aoffG + o] = tpl; tf[8160 + aoffG + o] = tph;
    }

    #pragma unroll
    for (int bb = 0; bb < 4; bb++) {
        __nv_bfloat16 vh = __float2bfloat16(a[bb]);
        __nv_bfloat16 vl = __float2bfloat16(a[bb] - __bfloat162float(vh));
        size_t r = (size_t)(bb * NPT + n);
        if (nextA) {
            __nv_bfloat16* row = nextA + r * KpNext;
            if (splitMode) {
                row[o] = vh; row[cout + o] = vl; row[2 * cout + o] = vh;
            } else {
                row[o] = vh;          row[cout + o] = tph;
                row[C2 + o] = vl;     row[C2 + cout + o] = tpl;
                row[2 * C2 + o] = vh; row[2 * C2 + cout + o] = tph;
            }
        }
        __nv_bfloat16* fr = d_AfinA + r * KPFA;
        fr[aoffG + o] = vh; fr[4080 + aoffG + o] = vl; fr[8160 + aoffG + o] = vh;
    }
}

// ---------------- split-K reduce + tp broadcast ----------------
__global__ void reduceK() {
    int idx = blockIdx.x * 256 + threadIdx.x;
    if (idx >= BB * NPT * LATENT) return;
    float s = 0.f;
    #pragma unroll
    for (int p = 0; p < NSPLIT; p++) s += d_part[(size_t)p * BB * NPT * LATENT + idx];
    int n = (idx >> 8) & 255, o = idx & 255;
    float t = 0.f;
    #pragma unroll
    for (int p = 0; p < NSPLIT2; p++) t += d_part2[(size_t)p * NPT * LATENT + n * LATENT + o];
    d_yt[idx] = s + t;
}

// ---------------- final-layer stats ----------------
__global__ __launch_bounds__(256) void final_stats() {
    int o = blockIdx.x;
    int tid = threadIdx.x;
    double s = 0.0, sq = 0.0;
    for (int r = tid; r < BB * NPT; r += 256) {
        float v = d_yt[(size_t)r * LATENT + o];
        s += (double)v;
        sq += (double)v * (double)v;
    }
    __shared__ double sh1[256], sh2[256];
    sh1[tid] = s; sh2[tid] = sq;
    __syncthreads();
    for (int st = 128; st > 0; st >>= 1) {
        if (tid < st) { sh1[tid] += sh1[tid + st]; sh2[tid] += sh2[tid + st]; }
        __syncthreads();
    }
    if (tid == 0) { d_S1[STAT_FIN + o] = sh1[0]; d_S2[STAT_FIN + o] = sh2[0]; }
}

// ---------------- write output: (bb, o, n), BN affine inline ----------------
__global__ void write_out(float* __restrict__ out, const float* __restrict__ g,
                          const float* __restrict__ beta) {
    int idx = blockIdx.x * blockDim.x + threadIdx.x;
    if (idx >= BB * LATENT * NPT) return;
    int n  = idx % NPT;
    int o  = (idx / NPT) % LATENT;
    int bb = idx / (NPT * LATENT);
    float invcnt = 1.f / (float)(BB * NPT);
    float mean = (float)(d_S1[STAT_FIN + o] * (double)invcnt);
    float var  = (float)(d_S2[STAT_FIN + o] * (double)invcnt) - mean * mean;
    float sc = g[o] * rsqrtf(var + 1e-5f);
    float bi = beta[o] - mean * sc;
    float v = d_yt[(size_t)(bb * NPT + n) * LATENT + o];
    float y = v * sc + bi;
    out[idx] = (y >= 0.f) ? y : 0.2f * y;
}

// ---------------- orchestration ----------------
extern "C" void kernel_launch(void* const* d_in, const int* in_sizes, int n_in,
                              void* d_out, int out_size) {
    const float* x = (const float*)d_in[0];
    const float* w[5]; const float* g[5]; const float* bt[5];
    for (int i = 0; i < 5; i++) {
        w[i]  = (const float*)d_in[1 + 3 * i];
        g[i]  = (const float*)d_in[2 + 3 * i];
        bt[i] = (const float*)d_in[3 + 3 * i];
    }
    float* out = (float*)d_out;

    float *UV_p, *G2_p, *part_p, *part2_p;
    __nv_bfloat16 *AfinA_p, *TPfin_p, *A0_p, *A1_p, *A2_p, *A3a_p, *TP3_p;
    __nv_bfloat16 *B0_p, *B1_p, *B2_p, *B3a_p, *B3tp_p, *BfA_p, *BfTP_p;
    cudaGetSymbolAddress((void**)&UV_p,    d_UV);
    cudaGetSymbolAddress((void**)&G2_p,    d_G2);
    cudaGetSymbolAddress((void**)&part_p,  d_part);
    cudaGetSymbolAddress((void**)&part2_p, d_part2);
    cudaGetSymbolAddress((void**)&AfinA_p, d_AfinA);
    cudaGetSymbolAddress((void**)&TPfin_p, d_TPfin);
    cudaGetSymbolAddress((void**)&A0_p,    d_A0);
    cudaGetSymbolAddress((void**)&A1_p,    d_A1);
    cudaGetSymbolAddress((void**)&A2_p,    d_A2);
    cudaGetSymbolAddress((void**)&A3a_p,   d_A3a);
    cudaGetSymbolAddress((void**)&TP3_p,   d_TP3);
    cudaGetSymbolAddress((void**)&B0_p,    d_B0);
    cudaGetSymbolAddress((void**)&B1_p,    d_B1);
    cudaGetSymbolAddress((void**)&B2_p,    d_B2);
    cudaGetSymbolAddress((void**)&B3a_p,   d_B3a);
    cudaGetSymbolAddress((void**)&B3tp_p,  d_B3tp);
    cudaGetSymbolAddress((void**)&BfA_p,   d_BfA);
    cudaGetSymbolAddress((void**)&BfTP_p,  d_BfTP);

    cudaFuncSetAttribute(gemm_mma, cudaFuncAttributeMaxDynamicSharedMemorySize,
                         NSTAGE * STG_BYTES);

    prep_all<<<(PREP_TOT + 255) / 256, 256>>>(x, w[0], w[1], w[2], w[3], w[4]);
    knn_kernel<<<BB * 32, 256>>>(x);

    const int M = BB * NPT;  // 1024

    // ---- layers 0..2 ----
    const int coL[3]   = {48, 192, 768};
    const int kpadL[3] = {128, 384, 1152};
    const int npadL[3] = {128, 384, 1536};
    const int statL[3] = {0, 48, 240};
    __nv_bfloat16* AbufL[3] = {A0_p, A1_p, A2_p};
    __nv_bfloat16* BbufL[3] = {B0_p, B1_p, B2_p};

    for (int l = 0; l < 3; l++) {
        int twoc = 2 * coL[l];
        int Kp = kpadL[l], Np = npadL[l];
        int totCh = Kp / 64;

        gemm_mma<<<dim3(Np / 128, M / 128, 1), 256, NSTAGE * STG_BYTES>>>(
            AbufL[l], Kp, BbufL[l], Kp, UV_p, twoc, twoc, totCh, totCh, 0, nullptr);

        dim3 gg((coL[l] + 127) / 128, M / 8);
        gather_stats_max<<<gg, 128>>>(coL[l], 8, statL[l]);

        if (l < 2) {
            act_pool<<<(NPT * coL[l] + 255) / 256, 256>>>(
                coL[l], statL[l], kpadL[l + 1], AbufL[l + 1], (__nv_bfloat16*)nullptr, 0,
                statL[l], g[l], bt[l], 1.f / (float)(M * KNN));
        } else {
            act_pool<<<(NPT * coL[l] + 255) / 256, 256>>>(
                coL[l], statL[l], 2304, A3a_p, TP3_p, 1,
                statL[l], g[l], bt[l], 1.f / (float)(M * KNN));
        }
    }

    // ---- layer 3: split GEMM (a-part M=1024, tp-part M=256 broadcast) ----
    {
        int Kp = 2304, Np = 6144, totCh = Kp / 64;  // 36 chunks
        gemm_mma<<<dim3(Np / 128, 2, 1), 256, NSTAGE * STG_BYTES>>>(
            TP3_p, Kp, B3tp_p, Kp, G2_p, 6144, 6144, totCh, totCh, 0, nullptr);
        gemm_mma<<<dim3(Np / 128, M / 128, 1), 256, NSTAGE * STG_BYTES>>>(
            A3a_p, Kp, B3a_p, Kp, UV_p, 6144, 6144, totCh, totCh, 0, G2_p);

        dim3 gg((3072 + 127) / 128, M / 8);
        gather_stats_max<<<gg, 128>>>(3072, 8, 1008);
        act_pool<<<(NPT * 3072 + 255) / 256, 256>>>(
            3072, 1008, 0, (__nv_bfloat16*)nullptr, (__nv_bfloat16*)nullptr, 0,
            1008, g[3], bt[3], 1.f / (float)(M * KNN));
    }

    // ---- final: Ya = AfinA . BfA^T (split-K 16) + TP broadcast (split-K 16) ----
    {
        int totCh = KPFA / 64;   // 192 chunks
        gemm_mma<<<dim3(LATENT / 128, M / 128, NSPLIT), 256, NSTAGE * STG_BYTES>>>(
            AfinA_p, KPFA, BfA_p, KPFA, part_p, LATENT, LATENT,
            totCh, totCh / NSPLIT, (long long)M * LATENT, nullptr);
        gemm_mma<<<dim3(LATENT / 128, NPT / 128, NSPLIT2), 256, NSTAGE * STG_BYTES>>>(
            TPfin_p, KPFA, BfTP_p, KPFA, part2_p, LATENT, LATENT,
            totCh, totCh / NSPLIT2, (long long)NPT * LATENT, nullptr);

        reduceK<<<(M * LATENT + 255) / 256, 256>>>();
    }
    final_stats<<<LATENT, 256>>>();
    write_out<<<(BB * LATENT * NPT + 255) / 256, 256>>>(out, g[4], bt[4]);
}

// round 14
// speedup vs baseline: 1.5992x; 1.0041x over previous
#include <cuda_runtime.h>
#include <cuda_bf16.h>
#include <math_constants.h>
#include <cstdint>

#define BB 4
#define NPT 256
#define KNN 27
#define XCAT 8160
#define LATENT 256
#define KPFA 12288
#define NSPLIT 16
#define NSPLIT2 16
#define STAT_FIN 4080
#define STAT_SZ  4336

// ---------------- scratch (device globals; zero-init at load, no allocation) ----------------
__device__ float         d_UV   [BB * NPT * 6144];
__device__ float         d_G2   [NPT * 6144];
__device__ float         d_M    [BB * NPT * 3072];
__device__ float         d_yt   [BB * NPT * LATENT];
__device__ float         d_part [NSPLIT * BB * NPT * LATENT];
__device__ float         d_part2[NSPLIT2 * NPT * LATENT];
__device__ __nv_bfloat16 d_A0   [1024 * 128];
__device__ __nv_bfloat16 d_A1   [1024 * 384];
__device__ __nv_bfloat16 d_A2   [1024 * 1152];
__device__ __nv_bfloat16 d_A3a  [1024 * 2304];
__device__ __nv_bfloat16 d_TP3  [256 * 2304];
__device__ __nv_bfloat16 d_AfinA[1024 * KPFA];
__device__ __nv_bfloat16 d_TPfin[256 * KPFA];
__device__ __nv_bfloat16 d_B0   [128 * 128];
__device__ __nv_bfloat16 d_B1   [384 * 384];
__device__ __nv_bfloat16 d_B2   [1536 * 1152];
__device__ __nv_bfloat16 d_B3a  [6144 * 2304];
__device__ __nv_bfloat16 d_B3tp [6144 * 2304];
__device__ __nv_bfloat16 d_BfA  [256 * KPFA];
__device__ __nv_bfloat16 d_BfTP [256 * KPFA];
__device__ int           d_idx  [BB * NPT * KNN];
__device__ double        d_S1   [STAT_SZ];
__device__ double        d_S2   [STAT_SZ];

__device__ __forceinline__ uint32_t smem_u32(const void* p) {
    return (uint32_t)__cvta_generic_to_shared(p);
}

// ---------------- KNN: warp per point, strict-< argmin ----------------
__global__ void knn_kernel(const float* __restrict__ x) {
    int b     = blockIdx.x >> 5;
    int chunk = blockIdx.x & 31;
    int tid   = threadIdx.x;
    int wid   = tid >> 5;
    int lane  = tid & 31;
    int i     = chunk * 8 + wid;

    __shared__ float px[NPT], py[NPT], pz[NPT];
    const float* xb = x + (size_t)b * NPT * 3;
    px[tid] = xb[tid * 3 + 0];
    py[tid] = xb[tid * 3 + 1];
    pz[tid] = xb[tid * 3 + 2];
    __syncthreads();

    float xi = px[i], yi = py[i], zi = pz[i];
    float dloc[8];
    #pragma unroll
    for (int q = 0; q < 8; q++) {
        int j = lane + q * 32;
        float dx = xi - px[j], dy = yi - py[j], dz = zi - pz[j];
        dloc[q] = dx * dx + dy * dy + dz * dz;
    }
    unsigned chosen = 0;
    for (int s = 0; s < KNN; s++) {
        float bd = CUDART_INF_F;
        int   bj = 0x7fffffff;
        #pragma unroll
        for (int q = 0; q < 8; q++) {
            if (chosen & (1u << q)) continue;
            int j = lane + q * 32;
            float d = dloc[q];
            if (d < bd || (d == bd && j < bj)) { bd = d; bj = j; }
        }
        #pragma unroll
        for (int off = 16; off > 0; off >>= 1) {
            float od = __shfl_xor_sync(0xffffffffu, bd, off);
            int   oj = __shfl_xor_sync(0xffffffffu, bj, off);
            if (od < bd || (od == bd && oj < bj)) { bd = od; bj = oj; }
        }
        if ((bj & 31) == lane) chosen |= (1u << (bj >> 5));
        if (lane == 0) d_idx[((size_t)(b * NPT + i)) * KNN + s] = bj;
    }
}

// ---------------- element helpers for prep ----------------
__device__ __forceinline__ __nv_bfloat16 convB_elem(
    const float* __restrict__ w, int cout, int chFull, int c0, int Csub,
    int Kpad, int i, int mode)
{
    int r = i / Kpad, k = i % Kpad;
    int kk = (k < Csub) ? k : (k < 2 * Csub ? k - Csub : (k < 3 * Csub ? k - 2 * Csub : -1));
    float f = 0.f;
    if (kk >= 0) {
        int c = c0 + kk;
        if (mode) {
            if (r < cout) f = w[(size_t)r * 2 * chFull + c];
            else if (r < 2 * cout)
                f = w[(size_t)(r - cout) * 2 * chFull + chFull + c] - w[(size_t)(r - cout) * 2 * chFull + c];
        } else {
            f = w[(size_t)r * chFull + c];
        }
    }
    if (kk < 0) return __float2bfloat16(0.f);
    if (k < 2 * Csub) return __float2bfloat16(f);
    __nv_bfloat16 h = __float2bfloat16(f);
    return __float2bfloat16(f - __bfloat162float(h));
}

__device__ __forceinline__ __nv_bfloat16 convBfin_elem(
    const float* __restrict__ w4, int isTP, int i)
{
    int r = i / KPFA, k = i % KPFA;
    int kk = (k < 4080) ? k : (k < 8160 ? k - 4080 : (k < 12240 ? k - 8160 : -1));
    float f = 0.f;
    if (kk >= 0) {
        int l = (kk < 48) ? 0 : (kk < 240) ? 1 : (kk < 1008) ? 2 : 3;
        const int aoff[4] = {0, 48, 240, 1008};
        const int xoff[4] = {0, 96, 480, 2016};
        const int co[4]   = {48, 192, 768, 3072};
        int c = xoff[l] + (kk - aoff[l]) + (isTP ? co[l] : 0);
        f = w4[(size_t)r * XCAT + c];
    }
    if (kk < 0) return __float2bfloat16(0.f);
    if (k < 8160) return __float2bfloat16(f);
    __nv_bfloat16 h = __float2bfloat16(f);
    return __float2bfloat16(f - __bfloat162float(h));
}

// ---------------- mega prep: A0 + all B conversions + stat zero, ONE launch ----------------
#define PC0 131072            // A0: 1024*128
#define PC1 (PC0 + 16384)     // B0: 128*128
#define PC2 (PC1 + 147456)    // B1: 384*384
#define PC3 (PC2 + 1769472)   // B2: 1536*1152
#define PC4 (PC3 + 14155776)  // B3a: 6144*2304
#define PC5 (PC4 + 14155776)  // B3tp
#define PC6 (PC5 + 3145728)   // BfA: 256*12288
#define PC7 (PC6 + 3145728)   // BfTP
#define PC8 (PC7 + STAT_SZ)   // stats zero
#define PREP_TOT PC8

__global__ void prep_all(const float* __restrict__ x,
                         const float* __restrict__ w0, const float* __restrict__ w1,
                         const float* __restrict__ w2, const float* __restrict__ w3,
                         const float* __restrict__ w4) {
    int idx = blockIdx.x * 256 + threadIdx.x;
    if (idx >= PREP_TOT) return;
    if (idx < PC0) {
        int r = idx >> 7, k = idx & 127;
        __nv_bfloat16 o;
        if (k < 3) {
            o = __float2bfloat16(x[r * 3 + k]);
        } else if (k < 6) {
            float f = x[r * 3 + (k - 3)];
            __nv_bfloat16 h = __float2bfloat16(f);
            o = __float2bfloat16(f - __bfloat162float(h));
        } else if (k < 9) {
            o = __float2bfloat16(x[r * 3 + (k - 6)]);
        } else {
            o = __float2bfloat16(0.f);
        }
        d_A0[idx] = o;
    } else if (idx < PC1) {
        int i = idx - PC0;
        d_B0[i] = convB_elem(w0, 48, 3, 0, 3, 128, i, 1);
    } else if (idx < PC2) {
        int i = idx - PC1;
        d_B1[i] = convB_elem(w1, 192, 96, 0, 96, 384, i, 1);
    } else if (idx < PC3) {
        int i = idx - PC2;
        d_B2[i] = convB_elem(w2, 768, 384, 0, 384, 1152, i, 1);
    } else if (idx < PC4) {
        int i = idx - PC3;
        d_B3a[i] = convB_elem(w3, 3072, 1536, 0, 768, 2304, i, 1);
    } else if (idx < PC5) {
        int i = idx - PC4;
        d_B3tp[i] = convB_elem(w3, 3072, 1536, 768, 768, 2304, i, 1);
    } else if (idx < PC6) {
        int i = idx - PC5;
        d_BfA[i] = convBfin_elem(w4, 0, i);
    } else if (idx < PC7) {
        int i = idx - PC6;
        d_BfTP[i] = convBfin_elem(w4, 1, i);
    } else {
        int i = idx - PC7;
        d_S1[i] = 0.0; d_S2[i] = 0.0;
    }
}

// ---------------- bf16 HMMA GEMM, 3-stage cp.async pipeline (R9 config) ----------------
#define SW(off) ((off) ^ (((off) >> 3) & 0x70))
#define NSTAGE 3
#define STG_BYTES 32768

__device__ __forceinline__ void issue_stage(
    const __nv_bfloat16* Ag, int ldA, const __nv_bfloat16* Bg, int ldB,
    uint32_t sA, uint32_t sB, int tid)
{
    #pragma unroll
    for (int q = 0; q < 4; q++) {
        int u = tid + q * 256;
        int r = u >> 3, c16 = u & 7;
        uint32_t off = SW((uint32_t)(r * 128 + c16 * 16));
        asm volatile("cp.async.cg.shared.global [%0], [%1], 16;"
                     :: "r"(sA + off), "l"(Ag + (size_t)r * ldA + c16 * 8));
        asm volatile("cp.async.cg.shared.global [%0], [%1], 16;"
                     :: "r"(sB + off), "l"(Bg + (size_t)r * ldB + c16 * 8));
    }
}

__global__ __launch_bounds__(256, 1) void gemm_mma(
    const __nv_bfloat16* __restrict__ A, int ldA,
    const __nv_bfloat16* __restrict__ B, int ldB,
    float* __restrict__ C, int ldc, int Nc,
    int totCh, int chPer, long long splitStride,
    const float* __restrict__ addSrc)
{
    extern __shared__ __align__(128) unsigned char dyn[];
    uint32_t sb = smem_u32(dyn);

    int tid  = threadIdx.x;
    int wid  = tid >> 5;
    int lane = tid & 31;
    int m0 = blockIdx.y * 128, n0 = blockIdx.x * 128;
    int split = blockIdx.z;
    C += (long long)split * splitStride;
    int ks = split * chPer;
    int ke = min(ks + chPer, totCh);
    int nch = ke - ks;

    int wm0 = (wid >> 1) * 32;
    int wn0 = (wid & 1) * 64;

    float acc[2][8][4];
    #pragma unroll
    for (int i = 0; i < 2; i++)
        #pragma unroll
        for (int j = 0; j < 8; j++)
            #pragma unroll
            for (int c = 0; c < 4; c++) acc[i][j][c] = 0.f;

    const __nv_bfloat16* Abase = A + (size_t)m0 * ldA;
    const __nv_bfloat16* Bbase = B + (size_t)n0 * ldB;

    #pragma unroll
    for (int s = 0; s < NSTAGE - 1; s++) {
        if (s < nch)
            issue_stage(Abase + (size_t)(ks + s) * 64, ldA,
                        Bbase + (size_t)(ks + s) * 64, ldB,
                        sb + s * STG_BYTES, sb + s * STG_BYTES + 16384, tid);
        asm volatile("cp.async.commit_group;");
    }

    #pragma unroll 1
    for (int t = 0; t < nch; t++) {
        asm volatile("cp.async.wait_group %0;" :: "n"(NSTAGE - 2));
        __syncthreads();

        {
            int s = t + NSTAGE - 1;
            if (s < nch) {
                uint32_t sbase = sb + (s % NSTAGE) * STG_BYTES;
                issue_stage(Abase + (size_t)(ks + s) * 64, ldA,
                            Bbase + (size_t)(ks + s) * 64, ldB,
                            sbase, sbase + 16384, tid);
            }
            asm volatile("cp.async.commit_group;");
        }

        uint32_t sbA = sb + (t % NSTAGE) * STG_BYTES;
        uint32_t sbB = sbA + 16384;

        #pragma unroll
        for (int kkstep = 0; kkstep < 4; kkstep++) {
            uint32_t ra0[4], ra1[4], rb[4][4];
            int kb = kkstep * 32;
            {
                int r = lane & 7, sel = lane >> 3;
                int m = wm0 + r + (sel & 1) * 8;
                uint32_t off = SW((uint32_t)(m * 128 + kb + (sel >> 1) * 16));
                asm volatile("ldmatrix.sync.aligned.m8n8.x4.shared.b16 {%0,%1,%2,%3}, [%4];"
                             : "=r"(ra0[0]), "=r"(ra0[1]), "=r"(ra0[2]), "=r"(ra0[3])
                             : "r"(sbA + off));
                uint32_t off2 = SW((uint32_t)((m + 16) * 128 + kb + (sel >> 1) * 16));
                asm volatile("ldmatrix.sync.aligned.m8n8.x4.shared.b16 {%0,%1,%2,%3}, [%4];"
                             : "=r"(ra1[0]), "=r"(ra1[1]), "=r"(ra1[2]), "=r"(ra1[3])
                             : "r"(sbA + off2));
            }
            #pragma unroll
            for (int g = 0; g < 4; g++) {
                int r = lane & 7, sel = lane >> 3;
                int n = wn0 + g * 16 + r + (sel >> 1) * 8;
                uint32_t off = SW((uint32_t)(n * 128 + kb + (sel & 1) * 16));
                asm volatile("ldmatrix.sync.aligned.m8n8.x4.shared.b16 {%0,%1,%2,%3}, [%4];"
                             : "=r"(rb[g][0]), "=r"(rb[g][1]), "=r"(rb[g][2]), "=r"(rb[g][3])
                             : "r"(sbB + off));
            }
            #pragma unroll
            for (int g = 0; g < 4; g++) {
                #pragma unroll
                for (int half = 0; half < 2; half++) {
                    int j = g * 2 + half;
                    uint32_t b0 = rb[g][half * 2], b1 = rb[g][half * 2 + 1];
                    asm volatile(
                        "mma.sync.aligned.m16n8k16.row.col.f32.bf16.bf16.f32 "
                        "{%0,%1,%2,%3}, {%4,%5,%6,%7}, {%8,%9}, {%0,%1,%2,%3};"
                        : "+f"(acc[0][j][0]), "+f"(acc[0][j][1]),
                          "+f"(acc[0][j][2]), "+f"(acc[0][j][3])
                        : "r"(ra0[0]), "r"(ra0[1]), "r"(ra0[2]), "r"(ra0[3]),
                          "r"(b0), "r"(b1));
                    asm volatile(
                        "mma.sync.aligned.m16n8k16.row.col.f32.bf16.bf16.f32 "
                        "{%0,%1,%2,%3}, {%4,%5,%6,%7}, {%8,%9}, {%0,%1,%2,%3};"
                        : "+f"(acc[1][j][0]), "+f"(acc[1][j][1]),
                          "+f"(acc[1][j][2]), "+f"(acc[1][j][3])
                        : "r"(ra1[0]), "r"(ra1[1]), "r"(ra1[2]), "r"(ra1[3]),
                          "r"(b0), "r"(b1));
                }
            }
        }
    }

    #pragma unroll
    for (int mi = 0; mi < 2; mi++) {
        int mlo = m0 + wm0 + mi * 16 + (lane >> 2);
        #pragma unroll
        for (int j = 0; j < 8; j++) {
            int n = n0 + wn0 + j * 8 + (lane & 3) * 2;
            if (n < Nc) {
                float2 v0 = make_float2(acc[mi][j][0], acc[mi][j][1]);
                float2 v1 = make_float2(acc[mi][j][2], acc[mi][j][3]);
                if (addSrc) {
                    float2 a0 = *reinterpret_cast<const float2*>(
                        addSrc + (size_t)(mlo & 255) * ldc + n);
                    float2 a1 = *reinterpret_cast<const float2*>(
                        addSrc + (size_t)((mlo + 8) & 255) * ldc + n);
                    v0.x += a0.x; v0.y += a0.y;
                    v1.x += a1.x; v1.y += a1.y;
                }
                *reinterpret_cast<float2*>(C + (size_t)mlo * ldc + n) = v0;
                *reinterpret_cast<float2*>(C + (size_t)(mlo + 8) * ldc + n) = v1;
            }
        }
    }
}

// ---------------- gather + channel stats + max over k (batched loads for MLP) ----------------
__global__ __launch_bounds__(128) void gather_stats_max(int cout, int bn_per_blk, int statOff) {
    int o = blockIdx.x * 128 + threadIdx.x;
    int bnStart = blockIdx.y * bn_per_blk;
    bool active = (o < cout);
    int twoc = 2 * cout;
    double s1 = 0.0, s2 = 0.0;

    for (int t = 0; t < bn_per_blk; t++) {
        int bn = bnStart + t;
        int b  = bn >> 8;
        const int* ip = d_idx + (size_t)bn * KNN;
        if (!active) continue;
        float v = d_UV[(size_t)bn * twoc + cout + o];

        // phase 1: batch all 27 gathered loads (forces MLP=27)
        float uu[KNN];
        #pragma unroll
        for (int k = 0; k < KNN; k++) {
            int j = ip[k];
            uu[k] = d_UV[((size_t)(b * NPT + j)) * twoc + o];
        }
        // phase 2: accumulate from registers (same order as before)
        float mx = -CUDART_INF_F, s = 0.f, ssq = 0.f;
        #pragma unroll
        for (int k = 0; k < KNN; k++) {
            float u = uu[k];
            mx = fmaxf(mx, u);
            s += u;
            ssq += u * u;
        }
        d_M[(size_t)bn * cout + o] = mx + v;
        s1 += (double)(s + (float)KNN * v);
        s2 += (double)(ssq + 2.f * v * s + (float)KNN * v * v);
    }
    if (active) {
        atomicAdd(&d_S1[statOff + o], s1);
        atomicAdd(&d_S2[statOff + o], s2);
    }
}

// ---------------- activation + temporal pool + bf16 hi/lo operand writes ----------------
__global__ void act_pool(int cout, int aoffG, int KpNext,
                         __nv_bfloat16* __restrict__ nextA,
                         __nv_bfloat16* __restrict__ tpA, int splitMode,
                         int statOff, const float* __restrict__ g,
                         const float* __restrict__ beta, float invcnt) {
    int idx = blockIdx.x * blockDim.x + threadIdx.x;
    if (idx >= NPT * cout) return;
    int o = idx % cout, n = idx / cout;

    float mean = (float)(d_S1[statOff + o] * (double)invcnt);
    float var  = (float)(d_S2[statOff + o] * (double)invcnt) - mean * mean;
    float sc = g[o] * rsqrtf(var + 1e-5f);
    float bi = beta[o] - mean * sc;

    float a[4];
    #pragma unroll
    for (int bb = 0; bb < 4; bb++) {
        float m = d_M[(size_t)(bb * NPT + n) * cout + o];
        float y = m * sc + bi;
        a[bb] = (y >= 0.f) ? y : 0.2f * y;
    }
    float tp = 0.5f * (a[0] + a[1]);
    __nv_bfloat16 tph = __float2bfloat16(tp);
    __nv_bfloat16 tpl = __float2bfloat16(tp - __bfloat162float(tph));
    int C2 = 2 * cout;

    if (splitMode && tpA) {
        __nv_bfloat16* tr = tpA + (size_t)n * KpNext;
        tr[o] = tph; tr[cout + o] = tpl; tr[2 * cout + o] = tph;
    }
    {
        __nv_bfloat16* tf = d_TPfin + (size_t)n * KPFA;
        tf[aoffG + o] = tph; tf[4080 + aoffG + o] = tpl; tf[8160 + aoffG + o] = tph;
    }

    #pragma unroll
    for (int bb = 0; bb < 4; bb++) {
        __nv_bfloat16 vh = __float2bfloat16(a[bb]);
        __nv_bfloat16 vl = __float2bfloat16(a[bb] - __bfloat162float(vh));
        size_t r = (size_t)(bb * NPT + n);
        if (nextA) {
            __nv_bfloat16* row = nextA + r * KpNext;
            if (splitMode) {
                row[o] = vh; row[cout + o] = vl; row[2 * cout + o] = vh;
            } else {
                row[o] = vh;          row[cout + o] = tph;
                row[C2 + o] = vl;     row[C2 + cout + o] = tpl;
                row[2 * C2 + o] = vh; row[2 * C2 + cout + o] = tph;
            }
        }
        __nv_bfloat16* fr = d_AfinA + r * KPFA;
        fr[aoffG + o] = vh; fr[4080 + aoffG + o] = vl; fr[8160 + aoffG + o] = vh;
    }
}

// ---------------- split-K reduce + tp broadcast ----------------
__global__ void reduceK() {
    int idx = blockIdx.x * 256 + threadIdx.x;
    if (idx >= BB * NPT * LATENT) return;
    float s = 0.f;
    #pragma unroll
    for (int p = 0; p < NSPLIT; p++) s += d_part[(size_t)p * BB * NPT * LATENT + idx];
    int n = (idx >> 8) & 255, o = idx & 255;
    float t = 0.f;
    #pragma unroll
    for (int p = 0; p < NSPLIT2; p++) t += d_part2[(size_t)p * NPT * LATENT + n * LATENT + o];
    d_yt[idx] = s + t;
}

// ---------------- final-layer stats ----------------
__global__ __launch_bounds__(256) void final_stats() {
    int o = blockIdx.x;
    int tid = threadIdx.x;
    double s = 0.0, sq = 0.0;
    for (int r = tid; r < BB * NPT; r += 256) {
        float v = d_yt[(size_t)r * LATENT + o];
        s += (double)v;
        sq += (double)v * (double)v;
    }
    __shared__ double sh1[256], sh2[256];
    sh1[tid] = s; sh2[tid] = sq;
    __syncthreads();
    for (int st = 128; st > 0; st >>= 1) {
        if (tid < st) { sh1[tid] += sh1[tid + st]; sh2[tid] += sh2[tid + st]; }
        __syncthreads();
    }
    if (tid == 0) { d_S1[STAT_FIN + o] = sh1[0]; d_S2[STAT_FIN + o] = sh2[0]; }
}

// ---------------- write output: (bb, o, n), BN affine inline ----------------
__global__ void write_out(float* __restrict__ out, const float* __restrict__ g,
                          const float* __restrict__ beta) {
    int idx = blockIdx.x * blockDim.x + threadIdx.x;
    if (idx >= BB * LATENT * NPT) return;
    int n  = idx % NPT;
    int o  = (idx / NPT) % LATENT;
    int bb = idx / (NPT * LATENT);
    float invcnt = 1.f / (float)(BB * NPT);
    float mean = (float)(d_S1[STAT_FIN + o] * (double)invcnt);
    float var  = (float)(d_S2[STAT_FIN + o] * (double)invcnt) - mean * mean;
    float sc = g[o] * rsqrtf(var + 1e-5f);
    float bi = beta[o] - mean * sc;
    float v = d_yt[(size_t)(bb * NPT + n) * LATENT + o];
    float y = v * sc + bi;
    out[idx] = (y >= 0.f) ? y : 0.2f * y;
}

// ---------------- orchestration ----------------
extern "C" void kernel_launch(void* const* d_in, const int* in_sizes, int n_in,
                              void* d_out, int out_size) {
    const float* x = (const float*)d_in[0];
    const float* w[5]; const float* g[5]; const float* bt[5];
    for (int i = 0; i < 5; i++) {
        w[i]  = (const float*)d_in[1 + 3 * i];
        g[i]  = (const float*)d_in[2 + 3 * i];
        bt[i] = (const float*)d_in[3 + 3 * i];
    }
    float* out = (float*)d_out;

    float *UV_p, *G2_p, *part_p, *part2_p;
    __nv_bfloat16 *AfinA_p, *TPfin_p, *A0_p, *A1_p, *A2_p, *A3a_p, *TP3_p;
    __nv_bfloat16 *B0_p, *B1_p, *B2_p, *B3a_p, *B3tp_p, *BfA_p, *BfTP_p;
    cudaGetSymbolAddress((void**)&UV_p,    d_UV);
    cudaGetSymbolAddress((void**)&G2_p,    d_G2);
    cudaGetSymbolAddress((void**)&part_p,  d_part);
    cudaGetSymbolAddress((void**)&part2_p, d_part2);
    cudaGetSymbolAddress((void**)&AfinA_p, d_AfinA);
    cudaGetSymbolAddress((void**)&TPfin_p, d_TPfin);
    cudaGetSymbolAddress((void**)&A0_p,    d_A0);
    cudaGetSymbolAddress((void**)&A1_p,    d_A1);
    cudaGetSymbolAddress((void**)&A2_p,    d_A2);
    cudaGetSymbolAddress((void**)&A3a_p,   d_A3a);
    cudaGetSymbolAddress((void**)&TP3_p,   d_TP3);
    cudaGetSymbolAddress((void**)&B0_p,    d_B0);
    cudaGetSymbolAddress((void**)&B1_p,    d_B1);
    cudaGetSymbolAddress((void**)&B2_p,    d_B2);
    cudaGetSymbolAddress((void**)&B3a_p,   d_B3a);
    cudaGetSymbolAddress((void**)&B3tp_p,  d_B3tp);
    cudaGetSymbolAddress((void**)&BfA_p,   d_BfA);
    cudaGetSymbolAddress((void**)&BfTP_p,  d_BfTP);

    cudaFuncSetAttribute(gemm_mma, cudaFuncAttributeMaxDynamicSharedMemorySize,
                         NSTAGE * STG_BYTES);

    prep_all<<<(PREP_TOT + 255) / 256, 256>>>(x, w[0], w[1], w[2], w[3], w[4]);
    knn_kernel<<<BB * 32, 256>>>(x);

    const int M = BB * NPT;  // 1024

    // ---- layers 0..2 ----
    const int coL[3]   = {48, 192, 768};
    const int kpadL[3] = {128, 384, 1152};
    const int npadL[3] = {128, 384, 1536};
    const int statL[3] = {0, 48, 240};
    __nv_bfloat16* AbufL[3] = {A0_p, A1_p, A2_p};
    __nv_bfloat16* BbufL[3] = {B0_p, B1_p, B2_p};

    for (int l = 0; l < 3; l++) {
        int twoc = 2 * coL[l];
        int Kp = kpadL[l], Np = npadL[l];
        int totCh = Kp / 64;

        gemm_mma<<<dim3(Np / 128, M / 128, 1), 256, NSTAGE * STG_BYTES>>>(
            AbufL[l], Kp, BbufL[l], Kp, UV_p, twoc, twoc, totCh, totCh, 0, nullptr);

        dim3 gg((coL[l] + 127) / 128, M / 8);
        gather_stats_max<<<gg, 128>>>(coL[l], 8, statL[l]);

        if (l < 2) {
            act_pool<<<(NPT * coL[l] + 255) / 256, 256>>>(
                coL[l], statL[l], kpadL[l + 1], AbufL[l + 1], (__nv_bfloat16*)nullptr, 0,
                statL[l], g[l], bt[l], 1.f / (float)(M * KNN));
        } else {
            act_pool<<<(NPT * coL[l] + 255) / 256, 256>>>(
                coL[l], statL[l], 2304, A3a_p, TP3_p, 1,
                statL[l], g[l], bt[l], 1.f / (float)(M * KNN));
        }
    }

    // ---- layer 3: split GEMM (a-part M=1024, tp-part M=256 broadcast) ----
    {
        int Kp = 2304, Np = 6144, totCh = Kp / 64;  // 36 chunks
        gemm_mma<<<dim3(Np / 128, 2, 1), 256, NSTAGE * STG_BYTES>>>(
            TP3_p, Kp, B3tp_p, Kp, G2_p, 6144, 6144, totCh, totCh, 0, nullptr);
        gemm_mma<<<dim3(Np / 128, M / 128, 1), 256, NSTAGE * STG_BYTES>>>(
            A3a_p, Kp, B3a_p, Kp, UV_p, 6144, 6144, totCh, totCh, 0, G2_p);

        dim3 gg((3072 + 127) / 128, M / 8);
        gather_stats_max<<<gg, 128>>>(3072, 8, 1008);
        act_pool<<<(NPT * 3072 + 255) / 256, 256>>>(
            3072, 1008, 0, (__nv_bfloat16*)nullptr, (__nv_bfloat16*)nullptr, 0,
            1008, g[3], bt[3], 1.f / (float)(M * KNN));
    }

    // ---- final: Ya = AfinA . BfA^T (split-K 16) + TP broadcast (split-K 16) ----
    {
        int totCh = KPFA / 64;   // 192 chunks
        gemm_mma<<<dim3(LATENT / 128, M / 128, NSPLIT), 256, NSTAGE * STG_BYTES>>>(
            AfinA_p, KPFA, BfA_p, KPFA, part_p, LATENT, LATENT,
            totCh, totCh / NSPLIT, (long long)M * LATENT, nullptr);
        gemm_mma<<<dim3(LATENT / 128, NPT / 128, NSPLIT2), 256, NSTAGE * STG_BYTES>>>(
            TPfin_p, KPFA, BfTP_p, KPFA, part2_p, LATENT, LATENT,
            totCh, totCh / NSPLIT2, (long long)NPT * LATENT, nullptr);

        reduceK<<<(M * LATENT + 255) / 256, 256>>>();
    }
    final_stats<<<LATENT, 256>>>();
    write_out<<<(BB * LATENT * NPT + 255) / 256, 256>>>(out, g[4], bt[4]);
}

// round 15
// speedup vs baseline: 1.6309x; 1.0198x over previous
#include <cuda_runtime.h>
#include <cuda_bf16.h>
#include <math_constants.h>
#include <cstdint>

#define BB 4
#define NPT 256
#define KNN 27
#define XCAT 8160
#define LATENT 256
#define KPFA 12288
#define NSPLIT 16
#define NSPLIT2 16
#define STAT_FIN 4080
#define STAT_SZ  4336

// ---------------- scratch (device globals; zero-init at load, no allocation) ----------------
__device__ float         d_UV   [BB * NPT * 6144];
__device__ float         d_G2   [NPT * 6144];
__device__ float         d_M    [BB * NPT * 3072];
__device__ float         d_yt   [BB * NPT * LATENT];
__device__ float         d_part [NSPLIT * BB * NPT * LATENT];
__device__ float         d_part2[NSPLIT2 * NPT * LATENT];
__device__ __nv_bfloat16 d_A0   [1024 * 128];
__device__ __nv_bfloat16 d_A1   [1024 * 384];
__device__ __nv_bfloat16 d_A2   [1024 * 1152];
__device__ __nv_bfloat16 d_A3a  [1024 * 2304];
__device__ __nv_bfloat16 d_TP3  [256 * 2304];
__device__ __nv_bfloat16 d_AfinA[1024 * KPFA];
__device__ __nv_bfloat16 d_TPfin[256 * KPFA];
__device__ __nv_bfloat16 d_B0   [128 * 128];
__device__ __nv_bfloat16 d_B1   [384 * 384];
__device__ __nv_bfloat16 d_B2   [1536 * 1152];
__device__ __nv_bfloat16 d_B3a  [6144 * 2304];
__device__ __nv_bfloat16 d_B3tp [6144 * 2304];
__device__ __nv_bfloat16 d_BfA  [256 * KPFA];
__device__ __nv_bfloat16 d_BfTP [256 * KPFA];
__device__ int           d_idx  [BB * NPT * KNN];
__device__ double        d_S1   [STAT_SZ];
__device__ double        d_S2   [STAT_SZ];

__device__ __forceinline__ uint32_t smem_u32(const void* p) {
    return (uint32_t)__cvta_generic_to_shared(p);
}

// ---------------- KNN: warp per point, strict-< argmin ----------------
__global__ void knn_kernel(const float* __restrict__ x) {
    int b     = blockIdx.x >> 5;
    int chunk = blockIdx.x & 31;
    int tid   = threadIdx.x;
    int wid   = tid >> 5;
    int lane  = tid & 31;
    int i     = chunk * 8 + wid;

    __shared__ float px[NPT], py[NPT], pz[NPT];
    const float* xb = x + (size_t)b * NPT * 3;
    px[tid] = xb[tid * 3 + 0];
    py[tid] = xb[tid * 3 + 1];
    pz[tid] = xb[tid * 3 + 2];
    __syncthreads();

    float xi = px[i], yi = py[i], zi = pz[i];
    float dloc[8];
    #pragma unroll
    for (int q = 0; q < 8; q++) {
        int j = lane + q * 32;
        float dx = xi - px[j], dy = yi - py[j], dz = zi - pz[j];
        dloc[q] = dx * dx + dy * dy + dz * dz;
    }
    unsigned chosen = 0;
    for (int s = 0; s < KNN; s++) {
        float bd = CUDART_INF_F;
        int   bj = 0x7fffffff;
        #pragma unroll
        for (int q = 0; q < 8; q++) {
            if (chosen & (1u << q)) continue;
            int j = lane + q * 32;
            float d = dloc[q];
            if (d < bd || (d == bd && j < bj)) { bd = d; bj = j; }
        }
        #pragma unroll
        for (int off = 16; off > 0; off >>= 1) {
            float od = __shfl_xor_sync(0xffffffffu, bd, off);
            int   oj = __shfl_xor_sync(0xffffffffu, bj, off);
            if (od < bd || (od == bd && oj < bj)) { bd = od; bj = oj; }
        }
        if ((bj & 31) == lane) chosen |= (1u << (bj >> 5));
        if (lane == 0) d_idx[((size_t)(b * NPT + i)) * KNN + s] = bj;
    }
}

// ---------------- element helpers for prep ----------------
__device__ __forceinline__ __nv_bfloat16 convB_elem(
    const float* __restrict__ w, int cout, int chFull, int c0, int Csub,
    int Kpad, int i, int mode)
{
    int r = i / Kpad, k = i % Kpad;
    int kk = (k < Csub) ? k : (k < 2 * Csub ? k - Csub : (k < 3 * Csub ? k - 2 * Csub : -1));
    float f = 0.f;
    if (kk >= 0) {
        int c = c0 + kk;
        if (mode) {
            if (r < cout) f = w[(size_t)r * 2 * chFull + c];
            else if (r < 2 * cout)
                f = w[(size_t)(r - cout) * 2 * chFull + chFull + c] - w[(size_t)(r - cout) * 2 * chFull + c];
        } else {
            f = w[(size_t)r * chFull + c];
        }
    }
    if (kk < 0) return __float2bfloat16(0.f);
    if (k < 2 * Csub) return __float2bfloat16(f);
    __nv_bfloat16 h = __float2bfloat16(f);
    return __float2bfloat16(f - __bfloat162float(h));
}

__device__ __forceinline__ __nv_bfloat16 convBfin_elem(
    const float* __restrict__ w4, int isTP, int i)
{
    int r = i / KPFA, k = i % KPFA;
    int kk = (k < 4080) ? k : (k < 8160 ? k - 4080 : (k < 12240 ? k - 8160 : -1));
    float f = 0.f;
    if (kk >= 0) {
        int l = (kk < 48) ? 0 : (kk < 240) ? 1 : (kk < 1008) ? 2 : 3;
        const int aoff[4] = {0, 48, 240, 1008};
        const int xoff[4] = {0, 96, 480, 2016};
        const int co[4]   = {48, 192, 768, 3072};
        int c = xoff[l] + (kk - aoff[l]) + (isTP ? co[l] : 0);
        f = w4[(size_t)r * XCAT + c];
    }
    if (kk < 0) return __float2bfloat16(0.f);
    if (k < 8160) return __float2bfloat16(f);
    __nv_bfloat16 h = __float2bfloat16(f);
    return __float2bfloat16(f - __bfloat162float(h));
}

// ---------------- mega prep: A0 + all B conversions + stat zero, ONE launch ----------------
#define PC0 131072            // A0: 1024*128
#define PC1 (PC0 + 16384)     // B0: 128*128
#define PC2 (PC1 + 147456)    // B1: 384*384
#define PC3 (PC2 + 1769472)   // B2: 1536*1152
#define PC4 (PC3 + 14155776)  // B3a: 6144*2304
#define PC5 (PC4 + 14155776)  // B3tp
#define PC6 (PC5 + 3145728)   // BfA: 256*12288
#define PC7 (PC6 + 3145728)   // BfTP
#define PC8 (PC7 + STAT_SZ)   // stats zero
#define PREP_TOT PC8

__global__ void prep_all(const float* __restrict__ x,
                         const float* __restrict__ w0, const float* __restrict__ w1,
                         const float* __restrict__ w2, const float* __restrict__ w3,
                         const float* __restrict__ w4) {
    int idx = blockIdx.x * 256 + threadIdx.x;
    if (idx >= PREP_TOT) return;
    if (idx < PC0) {
        int r = idx >> 7, k = idx & 127;
        __nv_bfloat16 o;
        if (k < 3) {
            o = __float2bfloat16(x[r * 3 + k]);
        } else if (k < 6) {
            float f = x[r * 3 + (k - 3)];
            __nv_bfloat16 h = __float2bfloat16(f);
            o = __float2bfloat16(f - __bfloat162float(h));
        } else if (k < 9) {
            o = __float2bfloat16(x[r * 3 + (k - 6)]);
        } else {
            o = __float2bfloat16(0.f);
        }
        d_A0[idx] = o;
    } else if (idx < PC1) {
        int i = idx - PC0;
        d_B0[i] = convB_elem(w0, 48, 3, 0, 3, 128, i, 1);
    } else if (idx < PC2) {
        int i = idx - PC1;
        d_B1[i] = convB_elem(w1, 192, 96, 0, 96, 384, i, 1);
    } else if (idx < PC3) {
        int i = idx - PC2;
        d_B2[i] = convB_elem(w2, 768, 384, 0, 384, 1152, i, 1);
    } else if (idx < PC4) {
        int i = idx - PC3;
        d_B3a[i] = convB_elem(w3, 3072, 1536, 0, 768, 2304, i, 1);
    } else if (idx < PC5) {
        int i = idx - PC4;
        d_B3tp[i] = convB_elem(w3, 3072, 1536, 768, 768, 2304, i, 1);
    } else if (idx < PC6) {
        int i = idx - PC5;
        d_BfA[i] = convBfin_elem(w4, 0, i);
    } else if (idx < PC7) {
        int i = idx - PC6;
        d_BfTP[i] = convBfin_elem(w4, 1, i);
    } else {
        int i = idx - PC7;
        d_S1[i] = 0.0; d_S2[i] = 0.0;
    }
}

// ---------------- bf16 HMMA GEMM, 3-stage cp.async pipeline (R9 config) ----------------
#define SW(off) ((off) ^ (((off) >> 3) & 0x70))
#define NSTAGE 3
#define STG_BYTES 32768

__device__ __forceinline__ void issue_stage(
    const __nv_bfloat16* Ag, int ldA, const __nv_bfloat16* Bg, int ldB,
    uint32_t sA, uint32_t sB, int tid)
{
    #pragma unroll
    for (int q = 0; q < 4; q++) {
        int u = tid + q * 256;
        int r = u >> 3, c16 = u & 7;
        uint32_t off = SW((uint32_t)(r * 128 + c16 * 16));
        asm volatile("cp.async.cg.shared.global [%0], [%1], 16;"
                     :: "r"(sA + off), "l"(Ag + (size_t)r * ldA + c16 * 8));
        asm volatile("cp.async.cg.shared.global [%0], [%1], 16;"
                     :: "r"(sB + off), "l"(Bg + (size_t)r * ldB + c16 * 8));
    }
}

__global__ __launch_bounds__(256, 1) void gemm_mma(
    const __nv_bfloat16* __restrict__ A, int ldA,
    const __nv_bfloat16* __restrict__ B, int ldB,
    float* __restrict__ C, int ldc, int Nc,
    int totCh, int chPer, long long splitStride,
    const float* __restrict__ addSrc)
{
    extern __shared__ __align__(128) unsigned char dyn[];
    uint32_t sb = smem_u32(dyn);

    int tid  = threadIdx.x;
    int wid  = tid >> 5;
    int lane = tid & 31;
    int m0 = blockIdx.y * 128, n0 = blockIdx.x * 128;
    int split = blockIdx.z;
    C += (long long)split * splitStride;
    int ks = split * chPer;
    int ke = min(ks + chPer, totCh);
    int nch = ke - ks;

    int wm0 = (wid >> 1) * 32;
    int wn0 = (wid & 1) * 64;

    float acc[2][8][4];
    #pragma unroll
    for (int i = 0; i < 2; i++)
        #pragma unroll
        for (int j = 0; j < 8; j++)
            #pragma unroll
            for (int c = 0; c < 4; c++) acc[i][j][c] = 0.f;

    const __nv_bfloat16* Abase = A + (size_t)m0 * ldA;
    const __nv_bfloat16* Bbase = B + (size_t)n0 * ldB;

    #pragma unroll
    for (int s = 0; s < NSTAGE - 1; s++) {
        if (s < nch)
            issue_stage(Abase + (size_t)(ks + s) * 64, ldA,
                        Bbase + (size_t)(ks + s) * 64, ldB,
                        sb + s * STG_BYTES, sb + s * STG_BYTES + 16384, tid);
        asm volatile("cp.async.commit_group;");
    }

    #pragma unroll 1
    for (int t = 0; t < nch; t++) {
        asm volatile("cp.async.wait_group %0;" :: "n"(NSTAGE - 2));
        __syncthreads();

        {
            int s = t + NSTAGE - 1;
            if (s < nch) {
                uint32_t sbase = sb + (s % NSTAGE) * STG_BYTES;
                issue_stage(Abase + (size_t)(ks + s) * 64, ldA,
                            Bbase + (size_t)(ks + s) * 64, ldB,
                            sbase, sbase + 16384, tid);
            }
            asm volatile("cp.async.commit_group;");
        }

        uint32_t sbA = sb + (t % NSTAGE) * STG_BYTES;
        uint32_t sbB = sbA + 16384;

        #pragma unroll
        for (int kkstep = 0; kkstep < 4; kkstep++) {
            uint32_t ra0[4], ra1[4], rb[4][4];
            int kb = kkstep * 32;
            {
                int r = lane & 7, sel = lane >> 3;
                int m = wm0 + r + (sel & 1) * 8;
                uint32_t off = SW((uint32_t)(m * 128 + kb + (sel >> 1) * 16));
                asm volatile("ldmatrix.sync.aligned.m8n8.x4.shared.b16 {%0,%1,%2,%3}, [%4];"
                             : "=r"(ra0[0]), "=r"(ra0[1]), "=r"(ra0[2]), "=r"(ra0[3])
                             : "r"(sbA + off));
                uint32_t off2 = SW((uint32_t)((m + 16) * 128 + kb + (sel >> 1) * 16));
                asm volatile("ldmatrix.sync.aligned.m8n8.x4.shared.b16 {%0,%1,%2,%3}, [%4];"
                             : "=r"(ra1[0]), "=r"(ra1[1]), "=r"(ra1[2]), "=r"(ra1[3])
                             : "r"(sbA + off2));
            }
            #pragma unroll
            for (int g = 0; g < 4; g++) {
                int r = lane & 7, sel = lane >> 3;
                int n = wn0 + g * 16 + r + (sel >> 1) * 8;
                uint32_t off = SW((uint32_t)(n * 128 + kb + (sel & 1) * 16));
                asm volatile("ldmatrix.sync.aligned.m8n8.x4.shared.b16 {%0,%1,%2,%3}, [%4];"
                             : "=r"(rb[g][0]), "=r"(rb[g][1]), "=r"(rb[g][2]), "=r"(rb[g][3])
                             : "r"(sbB + off));
            }
            #pragma unroll
            for (int g = 0; g < 4; g++) {
                #pragma unroll
                for (int half = 0; half < 2; half++) {
                    int j = g * 2 + half;
                    uint32_t b0 = rb[g][half * 2], b1 = rb[g][half * 2 + 1];
                    asm volatile(
                        "mma.sync.aligned.m16n8k16.row.col.f32.bf16.bf16.f32 "
                        "{%0,%1,%2,%3}, {%4,%5,%6,%7}, {%8,%9}, {%0,%1,%2,%3};"
                        : "+f"(acc[0][j][0]), "+f"(acc[0][j][1]),
                          "+f"(acc[0][j][2]), "+f"(acc[0][j][3])
                        : "r"(ra0[0]), "r"(ra0[1]), "r"(ra0[2]), "r"(ra0[3]),
                          "r"(b0), "r"(b1));
                    asm volatile(
                        "mma.sync.aligned.m16n8k16.row.col.f32.bf16.bf16.f32 "
                        "{%0,%1,%2,%3}, {%4,%5,%6,%7}, {%8,%9}, {%0,%1,%2,%3};"
                        : "+f"(acc[1][j][0]), "+f"(acc[1][j][1]),
                          "+f"(acc[1][j][2]), "+f"(acc[1][j][3])
                        : "r"(ra1[0]), "r"(ra1[1]), "r"(ra1[2]), "r"(ra1[3]),
                          "r"(b0), "r"(b1));
                }
            }
        }
    }

    #pragma unroll
    for (int mi = 0; mi < 2; mi++) {
        int mlo = m0 + wm0 + mi * 16 + (lane >> 2);
        #pragma unroll
        for (int j = 0; j < 8; j++) {
            int n = n0 + wn0 + j * 8 + (lane & 3) * 2;
            if (n < Nc) {
                float2 v0 = make_float2(acc[mi][j][0], acc[mi][j][1]);
                float2 v1 = make_float2(acc[mi][j][2], acc[mi][j][3]);
                if (addSrc) {
                    float2 a0 = *reinterpret_cast<const float2*>(
                        addSrc + (size_t)(mlo & 255) * ldc + n);
                    float2 a1 = *reinterpret_cast<const float2*>(
                        addSrc + (size_t)((mlo + 8) & 255) * ldc + n);
                    v0.x += a0.x; v0.y += a0.y;
                    v1.x += a1.x; v1.y += a1.y;
                }
                *reinterpret_cast<float2*>(C + (size_t)mlo * ldc + n) = v0;
                *reinterpret_cast<float2*>(C + (size_t)(mlo + 8) * ldc + n) = v1;
            }
        }
    }
}

// ---------------- gather + channel stats + max over k ----------------
__global__ __launch_bounds__(128) void gather_stats_max(int cout, int bn_per_blk, int statOff) {
    int o = blockIdx.x * 128 + threadIdx.x;
    int bnStart = blockIdx.y * bn_per_blk;
    bool active = (o < cout);
    int twoc = 2 * cout;
    double s1 = 0.0, s2 = 0.0;

    for (int t = 0; t < bn_per_blk; t++) {
        int bn = bnStart + t;
        int b  = bn >> 8;
        const int* ip = d_idx + (size_t)bn * KNN;
        if (!active) continue;
        float v = d_UV[(size_t)bn * twoc + cout + o];

        float uu[KNN];
        #pragma unroll
        for (int k = 0; k < KNN; k++) {
            int j = ip[k];
            uu[k] = d_UV[((size_t)(b * NPT + j)) * twoc + o];
        }
        float mx = -CUDART_INF_F, s = 0.f, ssq = 0.f;
        #pragma unroll
        for (int k = 0; k < KNN; k++) {
            float u = uu[k];
            mx = fmaxf(mx, u);
            s += u;
            ssq += u * u;
        }
        d_M[(size_t)bn * cout + o] = mx + v;
        s1 += (double)(s + (float)KNN * v);
        s2 += (double)(ssq + 2.f * v * s + (float)KNN * v * v);
    }
    if (active) {
        atomicAdd(&d_S1[statOff + o], s1);
        atomicAdd(&d_S2[statOff + o], s2);
    }
}

// ---------------- activation + temporal pool + bf16 hi/lo operand writes ----------------
__global__ void act_pool(int cout, int aoffG, int KpNext,
                         __nv_bfloat16* __restrict__ nextA,
                         __nv_bfloat16* __restrict__ tpA, int splitMode,
                         int statOff, const float* __restrict__ g,
                         const float* __restrict__ beta, float invcnt) {
    int idx = blockIdx.x * blockDim.x + threadIdx.x;
    if (idx >= NPT * cout) return;
    int o = idx % cout, n = idx / cout;

    float mean = (float)(d_S1[statOff + o] * (double)invcnt);
    float var  = (float)(d_S2[statOff + o] * (double)invcnt) - mean * mean;
    float sc = g[o] * rsqrtf(var + 1e-5f);
    float bi = beta[o] - mean * sc;

    float a[4];
    #pragma unroll
    for (int bb = 0; bb < 4; bb++) {
        float m = d_M[(size_t)(bb * NPT + n) * cout + o];
        float y = m * sc + bi;
        a[bb] = (y >= 0.f) ? y : 0.2f * y;
    }
    float tp = 0.5f * (a[0] + a[1]);
    __nv_bfloat16 tph = __float2bfloat16(tp);
    __nv_bfloat16 tpl = __float2bfloat16(tp - __bfloat162float(tph));
    int C2 = 2 * cout;

    if (splitMode && tpA) {
        __nv_bfloat16* tr = tpA + (size_t)n * KpNext;
        tr[o] = tph; tr[cout + o] = tpl; tr[2 * cout + o] = tph;
    }
    {
        __nv_bfloat16* tf = d_TPfin + (size_t)n * KPFA;
        tf[aoffG + o] = tph; tf[4080 + aoffG + o] = tpl; tf[8160 + aoffG + o] = tph;
    }

    #pragma unroll
    for (int bb = 0; bb < 4; bb++) {
        __nv_bfloat16 vh = __float2bfloat16(a[bb]);
        __nv_bfloat16 vl = __float2bfloat16(a[bb] - __bfloat162float(vh));
        size_t r = (size_t)(bb * NPT + n);
        if (nextA) {
            __nv_bfloat16* row = nextA + r * KpNext;
            if (splitMode) {
                row[o] = vh; row[cout + o] = vl; row[2 * cout + o] = vh;
            } else {
                row[o] = vh;          row[cout + o] = tph;
                row[C2 + o] = vl;     row[C2 + cout + o] = tpl;
                row[2 * C2 + o] = vh; row[2 * C2 + cout + o] = tph;
            }
        }
        __nv_bfloat16* fr = d_AfinA + r * KPFA;
        fr[aoffG + o] = vh; fr[4080 + aoffG + o] = vl; fr[8160 + aoffG + o] = vh;
    }
}

// ---------------- split-K reduce + tp broadcast ----------------
__global__ void reduceK() {
    int idx = blockIdx.x * 256 + threadIdx.x;
    if (idx >= BB * NPT * LATENT) return;
    float s = 0.f;
    #pragma unroll
    for (int p = 0; p < NSPLIT; p++) s += d_part[(size_t)p * BB * NPT * LATENT + idx];
    int n = (idx >> 8) & 255, o = idx & 255;
    float t = 0.f;
    #pragma unroll
    for (int p = 0; p < NSPLIT2; p++) t += d_part2[(size_t)p * NPT * LATENT + n * LATENT + o];
    d_yt[idx] = s + t;
}

// ---------------- final-layer stats ----------------
__global__ __launch_bounds__(256) void final_stats() {
    int o = blockIdx.x;
    int tid = threadIdx.x;
    double s = 0.0, sq = 0.0;
    for (int r = tid; r < BB * NPT; r += 256) {
        float v = d_yt[(size_t)r * LATENT + o];
        s += (double)v;
        sq += (double)v * (double)v;
    }
    __shared__ double sh1[256], sh2[256];
    sh1[tid] = s; sh2[tid] = sq;
    __syncthreads();
    for (int st = 128; st > 0; st >>= 1) {
        if (tid < st) { sh1[tid] += sh1[tid + st]; sh2[tid] += sh2[tid + st]; }
        __syncthreads();
    }
    if (tid == 0) { d_S1[STAT_FIN + o] = sh1[0]; d_S2[STAT_FIN + o] = sh2[0]; }
}

// ---------------- write output: (bb, o, n), BN affine inline ----------------
__global__ void write_out(float* __restrict__ out, const float* __restrict__ g,
                          const float* __restrict__ beta) {
    int idx = blockIdx.x * blockDim.x + threadIdx.x;
    if (idx >= BB * LATENT * NPT) return;
    int n  = idx % NPT;
    int o  = (idx / NPT) % LATENT;
    int bb = idx / (NPT * LATENT);
    float invcnt = 1.f / (float)(BB * NPT);
    float mean = (float)(d_S1[STAT_FIN + o] * (double)invcnt);
    float var  = (float)(d_S2[STAT_FIN + o] * (double)invcnt) - mean * mean;
    float sc = g[o] * rsqrtf(var + 1e-5f);
    float bi = beta[o] - mean * sc;
    float v = d_yt[(size_t)(bb * NPT + n) * LATENT + o];
    float y = v * sc + bi;
    out[idx] = (y >= 0.f) ? y : 0.2f * y;
}

// ---------------- orchestration ----------------
extern "C" void kernel_launch(void* const* d_in, const int* in_sizes, int n_in,
                              void* d_out, int out_size) {
    const float* x = (const float*)d_in[0];
    const float* w[5]; const float* g[5]; const float* bt[5];
    for (int i = 0; i < 5; i++) {
        w[i]  = (const float*)d_in[1 + 3 * i];
        g[i]  = (const float*)d_in[2 + 3 * i];
        bt[i] = (const float*)d_in[3 + 3 * i];
    }
    float* out = (float*)d_out;

    float *UV_p, *G2_p, *part_p, *part2_p;
    __nv_bfloat16 *AfinA_p, *TPfin_p, *A0_p, *A1_p, *A2_p, *A3a_p, *TP3_p;
    __nv_bfloat16 *B0_p, *B1_p, *B2_p, *B3a_p, *B3tp_p, *BfA_p, *BfTP_p;
    cudaGetSymbolAddress((void**)&UV_p,    d_UV);
    cudaGetSymbolAddress((void**)&G2_p,    d_G2);
    cudaGetSymbolAddress((void**)&part_p,  d_part);
    cudaGetSymbolAddress((void**)&part2_p, d_part2);
    cudaGetSymbolAddress((void**)&AfinA_p, d_AfinA);
    cudaGetSymbolAddress((void**)&TPfin_p, d_TPfin);
    cudaGetSymbolAddress((void**)&A0_p,    d_A0);
    cudaGetSymbolAddress((void**)&A1_p,    d_A1);
    cudaGetSymbolAddress((void**)&A2_p,    d_A2);
    cudaGetSymbolAddress((void**)&A3a_p,   d_A3a);
    cudaGetSymbolAddress((void**)&TP3_p,   d_TP3);
    cudaGetSymbolAddress((void**)&B0_p,    d_B0);
    cudaGetSymbolAddress((void**)&B1_p,    d_B1);
    cudaGetSymbolAddress((void**)&B2_p,    d_B2);
    cudaGetSymbolAddress((void**)&B3a_p,   d_B3a);
    cudaGetSymbolAddress((void**)&B3tp_p,  d_B3tp);
    cudaGetSymbolAddress((void**)&BfA_p,   d_BfA);
    cudaGetSymbolAddress((void**)&BfTP_p,  d_BfTP);

    cudaFuncSetAttribute(gemm_mma, cudaFuncAttributeMaxDynamicSharedMemorySize,
                         NSTAGE * STG_BYTES);

    prep_all<<<(PREP_TOT + 255) / 256, 256>>>(x, w[0], w[1], w[2], w[3], w[4]);
    knn_kernel<<<BB * 32, 256>>>(x);

    const int M = BB * NPT;  // 1024

    // ---- layers 0..2 ----
    const int coL[3]   = {48, 192, 768};
    const int kpadL[3] = {128, 384, 1152};
    const int npadL[3] = {128, 384, 1536};
    const int statL[3] = {0, 48, 240};
    const int bnbL[3]  = {1, 2, 4};      // per-layer gather parallelism (>=1024 blocks)
    __nv_bfloat16* AbufL[3] = {A0_p, A1_p, A2_p};
    __nv_bfloat16* BbufL[3] = {B0_p, B1_p, B2_p};

    for (int l = 0; l < 3; l++) {
        int twoc = 2 * coL[l];
        int Kp = kpadL[l], Np = npadL[l];
        int totCh = Kp / 64;

        gemm_mma<<<dim3(Np / 128, M / 128, 1), 256, NSTAGE * STG_BYTES>>>(
            AbufL[l], Kp, BbufL[l], Kp, UV_p, twoc, twoc, totCh, totCh, 0, nullptr);

        dim3 gg((coL[l] + 127) / 128, M / bnbL[l]);
        gather_stats_max<<<gg, 128>>>(coL[l], bnbL[l], statL[l]);

        if (l < 2) {
            act_pool<<<(NPT * coL[l] + 255) / 256, 256>>>(
                coL[l], statL[l], kpadL[l + 1], AbufL[l + 1], (__nv_bfloat16*)nullptr, 0,
                statL[l], g[l], bt[l], 1.f / (float)(M * KNN));
        } else {
            act_pool<<<(NPT * coL[l] + 255) / 256, 256>>>(
                coL[l], statL[l], 2304, A3a_p, TP3_p, 1,
                statL[l], g[l], bt[l], 1.f / (float)(M * KNN));
        }
    }

    // ---- layer 3: split GEMM (a-part M=1024, tp-part M=256 broadcast) ----
    {
        int Kp = 2304, Np = 6144, totCh = Kp / 64;  // 36 chunks
        gemm_mma<<<dim3(Np / 128, 2, 1), 256, NSTAGE * STG_BYTES>>>(
            TP3_p, Kp, B3tp_p, Kp, G2_p, 6144, 6144, totCh, totCh, 0, nullptr);
        gemm_mma<<<dim3(Np / 128, M / 128, 1), 256, NSTAGE * STG_BYTES>>>(
            A3a_p, Kp, B3a_p, Kp, UV_p, 6144, 6144, totCh, totCh, 0, G2_p);

        dim3 gg((3072 + 127) / 128, M / 8);
        gather_stats_max<<<gg, 128>>>(3072, 8, 1008);
        act_pool<<<(NPT * 3072 + 255) / 256, 256>>>(
            3072, 1008, 0, (__nv_bfloat16*)nullptr, (__nv_bfloat16*)nullptr, 0,
            1008, g[3], bt[3], 1.f / (float)(M * KNN));
    }

    // ---- final: Ya = AfinA . BfA^T (split-K 16) + TP broadcast (split-K 16) ----
    {
        int totCh = KPFA / 64;   // 192 chunks
        gemm_mma<<<dim3(LATENT / 128, M / 128, NSPLIT), 256, NSTAGE * STG_BYTES>>>(
            AfinA_p, KPFA, BfA_p, KPFA, part_p, LATENT, LATENT,
            totCh, totCh / NSPLIT, (long long)M * LATENT, nullptr);
        gemm_mma<<<dim3(LATENT / 128, NPT / 128, NSPLIT2), 256, NSTAGE * STG_BYTES>>>(
            TPfin_p, KPFA, BfTP_p, KPFA, part2_p, LATENT, LATENT,
            totCh, totCh / NSPLIT2, (long long)NPT * LATENT, nullptr);

        reduceK<<<(M * LATENT + 255) / 256, 256>>>();
    }
    final_stats<<<LATENT, 256>>>();
    write_out<<<(BB * LATENT * NPT + 255) / 256, 256>>>(out, g[4], bt[4]);
}